// round 15
// baseline (speedup 1.0000x reference)
#include <cuda_runtime.h>
#include <cuda_bf16.h>
#include <math.h>

#define Nn     50000
#define Cc     128
#define D1     256
#define D2     64
#define Ereal  800000
#define Etot   (Ereal + Nn)
#define FULL   0xFFFFFFFFu
#define NBLK   ((Nn + 1023) / 1024)
#define AGGF   (1u << 30)
#define PREF   (1u << 31)
#define VMSK   0x3FFFFFFFu

// ---------------- scratch ------------------------------------------------------
__device__ unsigned short g_xh[(size_t)Nn * Cc];
__device__ unsigned short g_xl[(size_t)Nn * Cc];
__device__ unsigned short g_hh[(size_t)Nn * D1];
__device__ unsigned short g_hl[(size_t)Nn * D1];
__device__ unsigned short g_w1h[D1 * Cc];
__device__ unsigned short g_w1l[D1 * Cc];
__device__ unsigned short g_w2h[D2 * D1];
__device__ unsigned short g_w2l[D2 * D1];
__device__ float g_o [(size_t)Nn * D2];
__device__ float g_y [Nn];
__device__ float g_as[Nn];
__device__ float g_ad[Nn];
__device__ float g_as3[Nn];
__device__ float g_ad3[Nn];
__device__ float g_ps[Cc];
__device__ float g_pd[Cc];
__device__ int   g_cnt [Nn];      // zero-invariant (scan resets)
__device__ int   g_epos[Ereal];
__device__ int   g_rowptr[Nn + 1];
__device__ int   g_csr[Etot];
__device__ unsigned g_bsum[64];   // lookback flags; reset by agg128 blk0
__device__ int   g_scandone;      // scan completion counter; reset by agg128 blk0

__device__ __forceinline__ unsigned short bf_hi(float v, float& r) {
    __nv_bfloat16 h = __float2bfloat16(v);
    r = v - __bfloat162float(h);
    return __bfloat16_as_ushort(h);
}
__device__ __forceinline__ unsigned short bf_of(float v) {
    return __bfloat16_as_ushort(__float2bfloat16(v));
}
__device__ __forceinline__ unsigned pack_hi(float a, float b, float& ra, float& rb) {
    unsigned ha = bf_hi(a, ra), hb = bf_hi(b, rb);
    return (hb << 16) | ha;
}
__device__ __forceinline__ unsigned pack_bf(float a, float b) {
    return ((unsigned)bf_of(b) << 16) | bf_of(a);
}
__device__ __forceinline__ float elu1(float v) { return v > 0.f ? v : expm1f(v); }
__device__ __forceinline__ float lrelu(float l) { return l > 0.f ? l : 0.2f * l; }

// ---------------- K1: edge count (first) + weight split + parallel p=W1@a ------
#define W1BLK 128
#define W2BLK 64
#define PBLK  32
__global__ void prep_count(const int* __restrict__ ei,
                           const float* __restrict__ W1, const float* __restrict__ as1,
                           const float* __restrict__ ad1, const float* __restrict__ W2,
                           int edge4Blk) {
    int b = blockIdx.x;
    if (b < edge4Blk) {
        int t = b * blockDim.x + threadIdx.x;
        if (t * 4 >= Ereal) return;
        int4 d4 = ((const int4*)(ei + Ereal))[t];
        int e = t * 4;
        g_epos[e + 0] = atomicAdd(&g_cnt[d4.x], 1);
        g_epos[e + 1] = atomicAdd(&g_cnt[d4.y], 1);
        g_epos[e + 2] = atomicAdd(&g_cnt[d4.z], 1);
        g_epos[e + 3] = atomicAdd(&g_cnt[d4.w], 1);
    } else if (b < edge4Blk + W1BLK) {
        int idx = (b - edge4Blk) * 256 + threadIdx.x;
        int n = idx >> 7, k = idx & 127;
        float v = W1[(size_t)k * D1 + n];
        float r;
        g_w1h[idx] = bf_hi(v, r);
        g_w1l[idx] = bf_of(r);
    } else if (b < edge4Blk + W1BLK + W2BLK) {
        int idx = (b - edge4Blk - W1BLK) * 256 + threadIdx.x;
        int n = idx >> 8, k = idx & 255;
        float v = W2[(size_t)k * D2 + n];
        float r;
        g_w2h[idx] = bf_hi(v, r);
        g_w2l[idx] = bf_of(r);
    } else {
        int w = (b - edge4Blk - W1BLK - W2BLK) * 8 + (threadIdx.x >> 5);
        int lane = threadIdx.x & 31;
        int i = w & 127;
        const float* a = (w < 128) ? as1 : ad1;
        const float* row = W1 + (size_t)i * D1;
        float s = 0.f;
        #pragma unroll
        for (int j = 0; j < 8; j++) s += row[lane + j * 32] * a[lane + j * 32];
        #pragma unroll
        for (int o = 16; o; o >>= 1) s += __shfl_xor_sync(FULL, s, o);
        if (lane == 0) { if (w < 128) g_ps[i] = s; else g_pd[i] = s; }
    }
}

// ---------------- K2: lookback scan + alpha + place (one launch) ----------------
__global__ void scan_alpha_place(const float* __restrict__ x, const int* __restrict__ ei,
                                 int alphaBlk) {
    int b = blockIdx.x;
    if (b < NBLK) {
        __shared__ int wsum[32];
        __shared__ int bpref;
        int tid = threadIdx.x, lane = tid & 31, wid = tid >> 5;
        int i = b * 1024 + tid;
        int v = 0;
        if (i < Nn) {
            v = g_cnt[i] + 1;          // +1 self-loop
            g_cnt[i] = 0;              // restore zero-invariant
        }
        int p = v;
        #pragma unroll
        for (int o = 1; o < 32; o <<= 1) {
            int t = __shfl_up_sync(FULL, p, o);
            if (lane >= o) p += t;
        }
        if (lane == 31) wsum[wid] = p;
        __syncthreads();
        if (wid == 0) {
            int w = wsum[lane];
            #pragma unroll
            for (int o = 1; o < 32; o <<= 1) {
                int t = __shfl_up_sync(FULL, w, o);
                if (lane >= o) w += t;
            }
            wsum[lane] = w;
        }
        __syncthreads();
        if (tid == 0) {
            unsigned total = (unsigned)wsum[31];
            if (b == 0) {
                atomicExch(&g_bsum[0], total | PREF);
                bpref = 0;
            } else {
                atomicExch(&g_bsum[b], total | AGGF);
                int pref = 0;
                int j = b - 1;
                while (j >= 0) {
                    unsigned vv = *(volatile unsigned*)&g_bsum[j];
                    if (vv == 0u) continue;
                    pref += (int)(vv & VMSK);
                    if (vv & PREF) break;
                    j--;
                }
                atomicExch(&g_bsum[b], ((unsigned)pref + total) | PREF);
                bpref = pref;
            }
        }
        __syncthreads();
        int excl = bpref + (wid ? wsum[wid - 1] : 0) + p - v;
        if (i < Nn) {
            g_rowptr[i] = excl;
            g_csr[excl] = i;           // self-loop at slot 0
        }
        if (i == 0) g_rowptr[Nn] = Etot;
        __syncthreads();
        if (tid == 0) {
            __threadfence();
            atomicAdd(&g_scandone, 1);
        }
    } else if (b < NBLK + alphaBlk) {
        int gw = (b - NBLK) * 32 + (threadIdx.x >> 5);
        int lane = threadIdx.x & 31;
        if (gw >= Nn) return;
        float4 v = ((const float4*)(x + (size_t)gw * Cc))[lane];
        float4 p = ((const float4*)g_ps)[lane];
        float4 q = ((const float4*)g_pd)[lane];
        float s1 = v.x * p.x + v.y * p.y + v.z * p.z + v.w * p.w;
        float s2 = v.x * q.x + v.y * q.y + v.z * q.z + v.w * q.w;
        #pragma unroll
        for (int o = 16; o; o >>= 1) {
            s1 += __shfl_xor_sync(FULL, s1, o);
            s2 += __shfl_xor_sync(FULL, s2, o);
        }
        if (lane == 0) { g_as[gw] = s1; g_ad[gw] = s2; }
    } else {
        if (threadIdx.x == 0) {
            while (*(volatile int*)&g_scandone < NBLK) __nanosleep(64);
        }
        __syncthreads();
        int t = (b - NBLK - alphaBlk) * 1024 + threadIdx.x;
        if (t * 4 >= Ereal) return;
        int4 s4 = ((const int4*)ei)[t];
        int4 d4 = ((const int4*)(ei + Ereal))[t];
        int4 p4 = ((const int4*)g_epos)[t];
        g_csr[g_rowptr[d4.x] + 1 + p4.x] = s4.x;
        g_csr[g_rowptr[d4.y] + 1 + p4.y] = s4.y;
        g_csr[g_rowptr[d4.z] + 1 + p4.z] = s4.z;
        g_csr[g_rowptr[d4.w] + 1 + p4.w] = s4.w;
    }
}

// ================= split-bf16 MMA helpers =======================================
#define GS 12

__device__ __forceinline__ void mma_bf16(float (&c)[4], const unsigned* a, const unsigned* b) {
    asm volatile(
        "mma.sync.aligned.m16n8k16.row.col.f32.bf16.bf16.f32 "
        "{%0,%1,%2,%3}, {%4,%5,%6,%7}, {%8,%9}, {%0,%1,%2,%3};\n"
        : "+f"(c[0]), "+f"(c[1]), "+f"(c[2]), "+f"(c[3])
        : "r"(a[0]), "r"(a[1]), "r"(a[2]), "r"(a[3]), "r"(b[0]), "r"(b[1]));
}

// ---------- GEMM1: 512 threads, 128x128 tile, double-buffered smem --------------
__global__ void __launch_bounds__(512) gemm1_k(const unsigned short* __restrict__ Ah,
                                               const unsigned short* __restrict__ Al,
                                               const unsigned short* __restrict__ Bh,
                                               const unsigned short* __restrict__ Bl,
                                               unsigned short* __restrict__ Ch,
                                               unsigned short* __restrict__ Cl,
                                               const float* __restrict__ bias,
                                               int M) {
    constexpr int K = Cc;      // 128
    constexpr int N = D1;      // 256
    __shared__ unsigned AsH[2][128 * GS];
    __shared__ unsigned AsL[2][128 * GS];
    __shared__ unsigned BsH[2][128 * GS];
    __shared__ unsigned BsL[2][128 * GS];

    const int br = blockIdx.y * 128;
    const int bn = blockIdx.x * 128;
    const int tid = threadIdx.x;
    const int lane = tid & 31;
    const int warp = tid >> 5;          // 0..15
    const int wm = (warp >> 2) * 32;
    const int wn = (warp & 3) * 32;

    float acc[2][4][4];
    #pragma unroll
    for (int m = 0; m < 2; m++)
        #pragma unroll
        for (int n = 0; n < 4; n++)
            #pragma unroll
            for (int r = 0; r < 4; r++) acc[m][n][r] = 0.f;

    const int q = lane >> 2;
    const int rr = lane & 3;

    const int ldRow = tid >> 2;
    const int ldC   = (tid & 3) * 4;
    const int so    = ldRow * GS + (ldC >> 1);

    const uint2 Z2 = make_uint2(0u, 0u);
    uint2 aRh, aRl, bRh, bRl;
    bool aOK = (br + ldRow < M);
    aRh = aOK ? *(const uint2*)(Ah + (size_t)(br + ldRow) * K + ldC) : Z2;
    aRl = aOK ? *(const uint2*)(Al + (size_t)(br + ldRow) * K + ldC) : Z2;
    bRh = *(const uint2*)(Bh + (size_t)(bn + ldRow) * K + ldC);
    bRl = *(const uint2*)(Bl + (size_t)(bn + ldRow) * K + ldC);
    AsH[0][so] = aRh.x; AsH[0][so + 1] = aRh.y;
    AsL[0][so] = aRl.x; AsL[0][so + 1] = aRl.y;
    BsH[0][so] = bRh.x; BsH[0][so + 1] = bRh.y;
    BsL[0][so] = bRl.x; BsL[0][so + 1] = bRl.y;
    __syncthreads();

    for (int k0 = 0; k0 < K; k0 += 16) {
        const int cur = (k0 >> 4) & 1;
        const bool more = (k0 + 16 < K);
        if (more) {
            int kn = k0 + 16;
            aRh = aOK ? *(const uint2*)(Ah + (size_t)(br + ldRow) * K + kn + ldC) : Z2;
            aRl = aOK ? *(const uint2*)(Al + (size_t)(br + ldRow) * K + kn + ldC) : Z2;
            bRh = *(const uint2*)(Bh + (size_t)(bn + ldRow) * K + kn + ldC);
            bRl = *(const uint2*)(Bl + (size_t)(bn + ldRow) * K + kn + ldC);
        }
        {
            unsigned ah[2][4], al[2][4], bh[4][2], bl[4][2];
            #pragma unroll
            for (int m = 0; m < 2; m++) {
                int r0 = (wm + m * 16 + q) * GS + rr;
                ah[m][0] = AsH[cur][r0];
                ah[m][1] = AsH[cur][r0 + 8 * GS];
                ah[m][2] = AsH[cur][r0 + 4];
                ah[m][3] = AsH[cur][r0 + 8 * GS + 4];
                al[m][0] = AsL[cur][r0];
                al[m][1] = AsL[cur][r0 + 8 * GS];
                al[m][2] = AsL[cur][r0 + 4];
                al[m][3] = AsL[cur][r0 + 8 * GS + 4];
            }
            #pragma unroll
            for (int n = 0; n < 4; n++) {
                int nb = (wn + n * 8 + q) * GS + rr;
                bh[n][0] = BsH[cur][nb];
                bh[n][1] = BsH[cur][nb + 4];
                bl[n][0] = BsL[cur][nb];
                bl[n][1] = BsL[cur][nb + 4];
            }
            #pragma unroll
            for (int m = 0; m < 2; m++)
                #pragma unroll
                for (int n = 0; n < 4; n++) {
                    mma_bf16(acc[m][n], ah[m], bh[n]);
                    mma_bf16(acc[m][n], ah[m], bl[n]);
                    mma_bf16(acc[m][n], al[m], bh[n]);
                }
        }
        if (more) {
            int nb = cur ^ 1;
            AsH[nb][so] = aRh.x; AsH[nb][so + 1] = aRh.y;
            AsL[nb][so] = aRl.x; AsL[nb][so + 1] = aRl.y;
            BsH[nb][so] = bRh.x; BsH[nb][so + 1] = bRh.y;
            BsL[nb][so] = bRl.x; BsL[nb][so + 1] = bRl.y;
        }
        __syncthreads();
    }

    #pragma unroll
    for (int m = 0; m < 2; m++) {
        int row0 = br + wm + m * 16 + q;
        #pragma unroll
        for (int n = 0; n < 4; n++) {
            int col = bn + wn + n * 8 + rr * 2;
            float b0 = bias[col], b1v = bias[col + 1];
            float r0x, r0y, r1x, r1y;
            float v0x = elu1(acc[m][n][0] + b0), v0y = elu1(acc[m][n][1] + b1v);
            float v1x = elu1(acc[m][n][2] + b0), v1y = elu1(acc[m][n][3] + b1v);
            if (row0 < M) {
                *(unsigned*)(Ch + (size_t)row0 * N + col) = pack_hi(v0x, v0y, r0x, r0y);
                *(unsigned*)(Cl + (size_t)row0 * N + col) = pack_bf(r0x, r0y);
            }
            if (row0 + 8 < M) {
                *(unsigned*)(Ch + (size_t)(row0 + 8) * N + col) = pack_hi(v1x, v1y, r1x, r1y);
                *(unsigned*)(Cl + (size_t)(row0 + 8) * N + col) = pack_bf(r1x, r1y);
            }
        }
    }
}

// ---------- GEMM2: 256 threads, 128x64 tile, double-buffered, fused alpha -------
__global__ void __launch_bounds__(256) gemm2_k(const unsigned short* __restrict__ Ah,
                                               const unsigned short* __restrict__ Al,
                                               const unsigned short* __restrict__ Bh,
                                               const unsigned short* __restrict__ Bl,
                                               float* __restrict__ C,
                                               const float* __restrict__ av,
                                               const float* __restrict__ bv,
                                               int M) {
    constexpr int K = D1;   // 256
    constexpr int N = D2;   // 64
    constexpr int WN = 32, NF = 4;
    __shared__ unsigned AsH[2][128 * GS];
    __shared__ unsigned AsL[2][128 * GS];
    __shared__ unsigned BsH[2][64 * GS];
    __shared__ unsigned BsL[2][64 * GS];

    const int br = blockIdx.y * 128;
    const int tid = threadIdx.x;
    const int lane = tid & 31;
    const int warp = tid >> 5;
    const int wm = (warp >> 1) * 32;
    const int wn = (warp & 1) * WN;

    float acc[2][NF][4];
    #pragma unroll
    for (int m = 0; m < 2; m++)
        #pragma unroll
        for (int n = 0; n < NF; n++)
            #pragma unroll
            for (int r = 0; r < 4; r++) acc[m][n][r] = 0.f;

    const int q = lane >> 2;
    const int rr = lane & 3;

    const int aRow0 = tid >> 2,         aC0 = (tid & 3) * 4;
    const int aRow1 = (tid + 256) >> 2;
    const int so0 = aRow0 * GS + (aC0 >> 1);
    const int so1 = aRow1 * GS + (aC0 >> 1);
    const int bRow = tid >> 2;                  // 0..63
    const int sob  = bRow * GS + (aC0 >> 1);

    const uint2 Z2 = make_uint2(0u, 0u);
    const bool a0OK = (br + aRow0 < M), a1OK = (br + aRow1 < M);
    uint2 aRh0, aRl0, aRh1, aRl1, bRh, bRl;
    aRh0 = a0OK ? *(const uint2*)(Ah + (size_t)(br + aRow0) * K + aC0) : Z2;
    aRl0 = a0OK ? *(const uint2*)(Al + (size_t)(br + aRow0) * K + aC0) : Z2;
    aRh1 = a1OK ? *(const uint2*)(Ah + (size_t)(br + aRow1) * K + aC0) : Z2;
    aRl1 = a1OK ? *(const uint2*)(Al + (size_t)(br + aRow1) * K + aC0) : Z2;
    bRh = *(const uint2*)(Bh + (size_t)bRow * K + aC0);
    bRl = *(const uint2*)(Bl + (size_t)bRow * K + aC0);
    AsH[0][so0] = aRh0.x; AsH[0][so0 + 1] = aRh0.y;
    AsL[0][so0] = aRl0.x; AsL[0][so0 + 1] = aRl0.y;
    AsH[0][so1] = aRh1.x; AsH[0][so1 + 1] = aRh1.y;
    AsL[0][so1] = aRl1.x; AsL[0][so1 + 1] = aRl1.y;
    BsH[0][sob] = bRh.x; BsH[0][sob + 1] = bRh.y;
    BsL[0][sob] = bRl.x; BsL[0][sob + 1] = bRl.y;
    __syncthreads();

    for (int k0 = 0; k0 < K; k0 += 16) {
        const int cur = (k0 >> 4) & 1;
        const bool more = (k0 + 16 < K);
        if (more) {
            int kn = k0 + 16;
            aRh0 = a0OK ? *(const uint2*)(Ah + (size_t)(br + aRow0) * K + kn + aC0) : Z2;
            aRl0 = a0OK ? *(const uint2*)(Al + (size_t)(br + aRow0) * K + kn + aC0) : Z2;
            aRh1 = a1OK ? *(const uint2*)(Ah + (size_t)(br + aRow1) * K + kn + aC0) : Z2;
            aRl1 = a1OK ? *(const uint2*)(Al + (size_t)(br + aRow1) * K + kn + aC0) : Z2;
            bRh = *(const uint2*)(Bh + (size_t)bRow * K + kn + aC0);
            bRl = *(const uint2*)(Bl + (size_t)bRow * K + kn + aC0);
        }
        {
            unsigned ah[2][4], al[2][4], bh[NF][2], bl[NF][2];
            #pragma unroll
            for (int m = 0; m < 2; m++) {
                int r0 = (wm + m * 16 + q) * GS + rr;
                ah[m][0] = AsH[cur][r0];
                ah[m][1] = AsH[cur][r0 + 8 * GS];
                ah[m][2] = AsH[cur][r0 + 4];
                ah[m][3] = AsH[cur][r0 + 8 * GS + 4];
                al[m][0] = AsL[cur][r0];
                al[m][1] = AsL[cur][r0 + 8 * GS];
                al[m][2] = AsL[cur][r0 + 4];
                al[m][3] = AsL[cur][r0 + 8 * GS + 4];
            }
            #pragma unroll
            for (int n = 0; n < NF; n++) {
                int nb = (wn + n * 8 + q) * GS + rr;
                bh[n][0] = BsH[cur][nb];
                bh[n][1] = BsH[cur][nb + 4];
                bl[n][0] = BsL[cur][nb];
                bl[n][1] = BsL[cur][nb + 4];
            }
            #pragma unroll
            for (int m = 0; m < 2; m++)
                #pragma unroll
                for (int n = 0; n < NF; n++) {
                    mma_bf16(acc[m][n], ah[m], bh[n]);
                    mma_bf16(acc[m][n], ah[m], bl[n]);
                    mma_bf16(acc[m][n], al[m], bh[n]);
                }
        }
        if (more) {
            int nb = cur ^ 1;
            AsH[nb][so0] = aRh0.x; AsH[nb][so0 + 1] = aRh0.y;
            AsL[nb][so0] = aRl0.x; AsL[nb][so0 + 1] = aRl0.y;
            AsH[nb][so1] = aRh1.x; AsH[nb][so1 + 1] = aRh1.y;
            AsL[nb][so1] = aRl1.x; AsL[nb][so1 + 1] = aRl1.y;
            BsH[nb][sob] = bRh.x; BsH[nb][sob + 1] = bRh.y;
            BsL[nb][sob] = bRl.x; BsL[nb][sob + 1] = bRl.y;
        }
        __syncthreads();
    }

    #pragma unroll
    for (int m = 0; m < 2; m++) {
        int row0 = br + wm + m * 16 + q;
        #pragma unroll
        for (int n = 0; n < NF; n++) {
            int col = wn + n * 8 + rr * 2;
            if (row0 < M)
                *(float2*)(C + (size_t)row0 * N + col) = make_float2(acc[m][n][0], acc[m][n][1]);
            if (row0 + 8 < M)
                *(float2*)(C + (size_t)(row0 + 8) * N + col) = make_float2(acc[m][n][2], acc[m][n][3]);
        }
    }

    // fused alpha: g_as/g_ad = C-row . av/bv (block covers all 64 cols)
    {
        float* sAs = (float*)AsH;
        float* sAd = sAs + 128;
        if (tid < 128) { sAs[tid] = 0.f; sAd[tid] = 0.f; }
        __syncthreads();
        #pragma unroll
        for (int m = 0; m < 2; m++) {
            float pa = 0.f, pd = 0.f, qa = 0.f, qd = 0.f;
            #pragma unroll
            for (int n = 0; n < NF; n++) {
                int col = wn + n * 8 + rr * 2;
                float a0 = av[col], a1 = av[col + 1];
                float d0 = bv[col], d1 = bv[col + 1];
                pa += acc[m][n][0] * a0 + acc[m][n][1] * a1;
                pd += acc[m][n][0] * d0 + acc[m][n][1] * d1;
                qa += acc[m][n][2] * a0 + acc[m][n][3] * a1;
                qd += acc[m][n][2] * d0 + acc[m][n][3] * d1;
            }
            int r = wm + m * 16 + q;
            atomicAdd(&sAs[r], pa);     atomicAdd(&sAd[r], pd);
            atomicAdd(&sAs[r + 8], qa); atomicAdd(&sAd[r + 8], qd);
        }
        __syncthreads();
        if (tid < 128 && br + tid < M) {
            g_as[br + tid] = sAs[tid];
            g_ad[br + tid] = sAd[tid];
        }
    }
}

// ============ shared phase-1: per-warp coef/idx tables in smem ==================
__device__ __forceinline__ void softmax_coefs(
    int gw, int start, int end, const float* __restrict__ asrc, float adn,
    float* wc, int* wi, int lane, float& m_out, float& inv_den_out) {
    int i0 = 0, i1 = 0;
    float l0 = -3.0e38f, l1 = -3.0e38f;
    float m = -3.0e38f, s = 0.f;
    int e = start + lane;
    if (e < end) { i0 = g_csr[e]; l0 = lrelu(asrc[i0] + adn); m = l0; s = 1.f; }
    if (e + 32 < end) {
        i1 = g_csr[e + 32];
        l1 = lrelu(asrc[i1] + adn);
        float mn = fmaxf(m, l1);
        s = s * __expf(m - mn) + __expf(l1 - mn);
        m = mn;
    }
    for (int e2 = e + 64; e2 < end; e2 += 32) {
        float l = lrelu(asrc[g_csr[e2]] + adn);
        float mn = fmaxf(m, l);
        s = s * __expf(m - mn) + __expf(l - mn);
        m = mn;
    }
    #pragma unroll
    for (int off = 16; off; off >>= 1) {
        float mo = __shfl_xor_sync(FULL, m, off);
        float so = __shfl_xor_sync(FULL, s, off);
        float mn = fmaxf(m, mo);
        s = s * __expf(m - mn) + so * __expf(mo - mn);
        m = mn;
    }
    float inv_den = 1.f / s;
    wc[lane]      = __expf(l0 - m) * inv_den;
    wc[lane + 32] = __expf(l1 - m) * inv_den;
    wi[lane]      = i0;
    wi[lane + 32] = i1;
    __syncwarp();
    m_out = m; inv_den_out = inv_den;
}

// ---------------- agg layer 1 (+bsum/scandone reset in block 0) -----------------
__global__ void __launch_bounds__(256, 6) agg128_k(const float* __restrict__ x) {
    __shared__ __align__(16) float scoef[8][64];
    __shared__ __align__(16) int   sidx [8][64];
    if (blockIdx.x == 0) {
        if (threadIdx.x < 64) g_bsum[threadIdx.x] = 0u;
        if (threadIdx.x == 64) g_scandone = 0;
    }
    int gw   = (blockIdx.x * blockDim.x + threadIdx.x) >> 5;
    int lane = threadIdx.x & 31;
    int w    = (threadIdx.x >> 5);
    if (gw >= Nn) return;
    const int start = g_rowptr[gw];
    const int end   = g_rowptr[gw + 1];
    const int deg   = end - start;
    float m, inv_den;
    softmax_coefs(gw, start, end, g_as, g_ad[gw], scoef[w], sidx[w], lane, m, inv_den);
    const int nreg = deg < 64 ? deg : 64;
    const float* wc = scoef[w];
    const int*   wi = sidx[w];

    float4 a0 = make_float4(0.f, 0.f, 0.f, 0.f);
    int j = 0;
    for (; j + 8 <= nreg; j += 8) {
        float4 cA = *(const float4*)&wc[j];
        float4 cB = *(const float4*)&wc[j + 4];
        int4   iA = *(const int4*)&wi[j];
        int4   iB = *(const int4*)&wi[j + 4];
        float4 r0 = ((const float4*)(x + (size_t)iA.x * 128))[lane];
        float4 r1 = ((const float4*)(x + (size_t)iA.y * 128))[lane];
        float4 r2 = ((const float4*)(x + (size_t)iA.z * 128))[lane];
        float4 r3 = ((const float4*)(x + (size_t)iA.w * 128))[lane];
        float4 r4 = ((const float4*)(x + (size_t)iB.x * 128))[lane];
        float4 r5 = ((const float4*)(x + (size_t)iB.y * 128))[lane];
        float4 r6 = ((const float4*)(x + (size_t)iB.z * 128))[lane];
        float4 r7 = ((const float4*)(x + (size_t)iB.w * 128))[lane];
        a0.x += cA.x * r0.x + cA.y * r1.x + cA.z * r2.x + cA.w * r3.x
              + cB.x * r4.x + cB.y * r5.x + cB.z * r6.x + cB.w * r7.x;
        a0.y += cA.x * r0.y + cA.y * r1.y + cA.z * r2.y + cA.w * r3.y
              + cB.x * r4.y + cB.y * r5.y + cB.z * r6.y + cB.w * r7.y;
        a0.z += cA.x * r0.z + cA.y * r1.z + cA.z * r2.z + cA.w * r3.z
              + cB.x * r4.z + cB.y * r5.z + cB.z * r6.z + cB.w * r7.z;
        a0.w += cA.x * r0.w + cA.y * r1.w + cA.z * r2.w + cA.w * r3.w
              + cB.x * r4.w + cB.y * r5.w + cB.z * r6.w + cB.w * r7.w;
    }
    for (; j < nreg; j++) {
        float ca = wc[j];
        int   s0 = wi[j];
        float4 r0 = ((const float4*)(x + (size_t)s0 * 128))[lane];
        a0.x += ca * r0.x; a0.y += ca * r0.y; a0.z += ca * r0.z; a0.w += ca * r0.w;
    }
    for (int e2 = start + 64; e2 < end; e2++) {
        int sn = g_csr[e2];
        float c = __expf(lrelu(g_as[sn] + g_ad[gw]) - m) * inv_den;
        float4 r0 = ((const float4*)(x + (size_t)sn * 128))[lane];
        a0.x += c * r0.x; a0.y += c * r0.y; a0.z += c * r0.z; a0.w += c * r0.w;
    }
    float rx, ry, rz, rw;
    unsigned h01 = pack_hi(a0.x, a0.y, rx, ry);
    unsigned h23 = pack_hi(a0.z, a0.w, rz, rw);
    *(uint2*)(g_xh + (size_t)gw * 128 + lane * 4) = make_uint2(h01, h23);
    *(uint2*)(g_xl + (size_t)gw * 128 + lane * 4) = make_uint2(pack_bf(rx, ry), pack_bf(rz, rw));
}

// ---------------- agg layer 2 (+fused bias/ELU/W3 matvec) -----------------------
__global__ void __launch_bounds__(256, 6) agg64_k(const float* __restrict__ h,
                      float* __restrict__ out, const float* __restrict__ bias,
                      const float* __restrict__ W3, const float* __restrict__ as3,
                      const float* __restrict__ ad3) {
    __shared__ __align__(16) float scoef[8][64];
    __shared__ __align__(16) int   sidx [8][64];
    int gw   = (blockIdx.x * blockDim.x + threadIdx.x) >> 5;
    int lane = threadIdx.x & 31;
    int w    = (threadIdx.x >> 5);
    if (gw >= Nn) return;
    const int start = g_rowptr[gw];
    const int end   = g_rowptr[gw + 1];
    const int deg   = end - start;
    float m, inv_den;
    softmax_coefs(gw, start, end, g_as, g_ad[gw], scoef[w], sidx[w], lane, m, inv_den);
    const int nreg = deg < 64 ? deg : 64;
    const float* wc = scoef[w];
    const int*   wi = sidx[w];

    float2 a = make_float2(0.f, 0.f);
    int j = 0;
    for (; j + 8 <= nreg; j += 8) {
        float4 cA = *(const float4*)&wc[j];
        float4 cB = *(const float4*)&wc[j + 4];
        int4   iA = *(const int4*)&wi[j];
        int4   iB = *(const int4*)&wi[j + 4];
        float2 r0 = ((const float2*)(h + (size_t)iA.x * 64))[lane];
        float2 r1 = ((const float2*)(h + (size_t)iA.y * 64))[lane];
        float2 r2 = ((const float2*)(h + (size_t)iA.z * 64))[lane];
        float2 r3 = ((const float2*)(h + (size_t)iA.w * 64))[lane];
        float2 r4 = ((const float2*)(h + (size_t)iB.x * 64))[lane];
        float2 r5 = ((const float2*)(h + (size_t)iB.y * 64))[lane];
        float2 r6 = ((const float2*)(h + (size_t)iB.z * 64))[lane];
        float2 r7 = ((const float2*)(h + (size_t)iB.w * 64))[lane];
        a.x += cA.x * r0.x + cA.y * r1.x + cA.z * r2.x + cA.w * r3.x
             + cB.x * r4.x + cB.y * r5.x + cB.z * r6.x + cB.w * r7.x;
        a.y += cA.x * r0.y + cA.y * r1.y + cA.z * r2.y + cA.w * r3.y
             + cB.x * r4.y + cB.y * r5.y + cB.z * r6.y + cB.w * r7.y;
    }
    for (; j < nreg; j++) {
        float ca = wc[j];
        int   s0 = wi[j];
        float2 r0 = ((const float2*)(h + (size_t)s0 * 64))[lane];
        a.x += ca * r0.x; a.y += ca * r0.y;
    }
    for (int e2 = start + 64; e2 < end; e2++) {
        int sn = g_csr[e2];
        float c = __expf(lrelu(g_as[sn] + g_ad[gw]) - m) * inv_den;
        float2 r0 = ((const float2*)(h + (size_t)sn * 64))[lane];
        a.x += c * r0.x; a.y += c * r0.y;
    }
    float2 bvv = ((const float2*)bias)[lane];
    a.x = elu1(a.x + bvv.x); a.y = elu1(a.y + bvv.y);
    float2 wv = ((const float2*)W3)[lane];
    float dot = a.x * wv.x + a.y * wv.y;
    #pragma unroll
    for (int off = 16; off; off >>= 1) dot += __shfl_xor_sync(FULL, dot, off);
    if (lane == 0) {
        out[gw]   = dot;
        g_as3[gw] = dot * as3[0];
        g_ad3[gw] = dot * ad3[0];
    }
}

// ---------------- agg layer 3 (scalar) ------------------------------------------
__global__ void agg1_k(const float* __restrict__ h, float* __restrict__ out,
                       const float* __restrict__ bias) {
    int gw   = (blockIdx.x * blockDim.x + threadIdx.x) >> 5;
    int lane = threadIdx.x & 31;
    if (gw >= Nn) return;
    const int start = g_rowptr[gw];
    const int end   = g_rowptr[gw + 1];
    const float adn = g_ad3[gw];

    float m = -3.0e38f, s = 0.f;
    for (int e = start + lane; e < end; e += 32) {
        float l = lrelu(g_as3[g_csr[e]] + adn);
        float mn = fmaxf(m, l);
        s = s * __expf(m - mn) + __expf(l - mn);
        m = mn;
    }
    #pragma unroll
    for (int off = 16; off; off >>= 1) {
        float mo = __shfl_xor_sync(FULL, m, off);
        float so = __shfl_xor_sync(FULL, s, off);
        float mn = fmaxf(m, mo);
        s = s * __expf(m - mn) + so * __expf(mo - mn);
        m = mn;
    }
    const float inv_den = 1.f / s;
    float a = 0.f;
    for (int e = start + lane; e < end; e += 32) {
        int sn = g_csr[e];
        float c = __expf(lrelu(g_as3[sn] + adn) - m) * inv_den;
        a += c * h[sn];
    }
    #pragma unroll
    for (int off = 16; off; off >>= 1) a += __shfl_xor_sync(FULL, a, off);
    if (lane == 0) out[gw] = a + bias[0];
}

// =============================== launcher ======================================
extern "C" void kernel_launch(void* const* d_in, const int* in_sizes, int n_in,
                              void* d_out, int out_size) {
    const float* x  = (const float*)d_in[0];
    const int*   ei = (const int*)d_in[1];
    const float *W1 = (const float*)d_in[2],  *as1 = (const float*)d_in[3],
                *ad1 = (const float*)d_in[4], *b1  = (const float*)d_in[5];
    const float *W2 = (const float*)d_in[6],  *as2 = (const float*)d_in[7],
                *ad2 = (const float*)d_in[8], *b2  = (const float*)d_in[9];
    const float *W3 = (const float*)d_in[10], *as3 = (const float*)d_in[11],
                *ad3 = (const float*)d_in[12], *b3 = (const float*)d_in[13];
    float* out = (float*)d_out;

    unsigned short *pxh, *pxl, *phh, *phl, *pw1h, *pw1l, *pw2h, *pw2l;
    float *po, *py;
    cudaGetSymbolAddress((void**)&pxh, g_xh);
    cudaGetSymbolAddress((void**)&pxl, g_xl);
    cudaGetSymbolAddress((void**)&phh, g_hh);
    cudaGetSymbolAddress((void**)&phl, g_hl);
    cudaGetSymbolAddress((void**)&pw1h, g_w1h);
    cudaGetSymbolAddress((void**)&pw1l, g_w1l);
    cudaGetSymbolAddress((void**)&pw2h, g_w2h);
    cudaGetSymbolAddress((void**)&pw2l, g_w2l);
    cudaGetSymbolAddress((void**)&po, g_o);
    cudaGetSymbolAddress((void**)&py, g_y);

    const int TB = 256;
    const int warpNodeBlk = (Nn * 32 + TB - 1) / TB;
    const int edge4Blk    = (Ereal / 4 + TB - 1) / TB;
    const int alphaBlk    = (Nn + 31) / 32;
    const int place1024   = (Ereal / 4 + 1023) / 1024;
    const int mRows = (Nn + 127) / 128;

    prep_count<<<edge4Blk + W1BLK + W2BLK + PBLK, TB>>>(ei, W1, as1, ad1, W2, edge4Blk);
    scan_alpha_place<<<NBLK + alphaBlk + place1024, 1024>>>(x, ei, alphaBlk);

    // ---- layer 1 (aggregate-then-transform): 128 -> 256 ----
    agg128_k<<<warpNodeBlk, TB>>>(x);
    {
        dim3 grid(D1 / 128, mRows);
        gemm1_k<<<grid, 512>>>(pxh, pxl, pw1h, pw1l, phh, phl, b1, Nn);
    }
    // ---- layer 2: 256 -> 64 ----
    {
        dim3 grid(1, mRows);
        gemm2_k<<<grid, 256>>>(phh, phl, pw2h, pw2l, po, as2, ad2, Nn);
        agg64_k<<<warpNodeBlk, TB>>>(po, py, b2, W3, as3, ad3);
    }
    // ---- layer 3: 64 -> 1 ----
    agg1_k<<<warpNodeBlk, TB>>>(py, out, b3);
}

// round 16
// speedup vs baseline: 1.0112x; 1.0112x over previous
#include <cuda_runtime.h>
#include <cuda_bf16.h>
#include <math.h>

#define Nn     50000
#define Cc     128
#define D1     256
#define D2     64
#define Ereal  800000
#define Etot   (Ereal + Nn)
#define FULL   0xFFFFFFFFu
#define NBLK   ((Nn + 1023) / 1024)
#define AGGF   (1u << 30)
#define PREF   (1u << 31)
#define VMSK   0x3FFFFFFFu

// ---------------- scratch ------------------------------------------------------
__device__ unsigned short g_xh[(size_t)Nn * Cc];
__device__ unsigned short g_xl[(size_t)Nn * Cc];
__device__ unsigned short g_hh[(size_t)Nn * D1];
__device__ unsigned short g_hl[(size_t)Nn * D1];
__device__ unsigned short g_w1h[D1 * Cc];
__device__ unsigned short g_w1l[D1 * Cc];
__device__ unsigned short g_w2h[D2 * D1];
__device__ unsigned short g_w2l[D2 * D1];
__device__ float g_o [(size_t)Nn * D2];
__device__ float g_y [Nn];
__device__ float g_as[Nn];
__device__ float g_ad[Nn];
__device__ float g_as3[Nn];
__device__ float g_ad3[Nn];
__device__ float g_ps[Cc];
__device__ float g_pd[Cc];
__device__ int   g_cnt [Nn];      // zero-invariant (scan resets)
__device__ int   g_epos[Ereal];
__device__ int   g_rowptr[Nn + 1];
__device__ int   g_csr[Etot];
__device__ unsigned g_bsum[64];   // lookback flags; reset by agg128 blk0
__device__ int   g_scandone;      // scan completion counter; reset by agg128 blk0

__device__ __forceinline__ unsigned short bf_hi(float v, float& r) {
    __nv_bfloat16 h = __float2bfloat16(v);
    r = v - __bfloat162float(h);
    return __bfloat16_as_ushort(h);
}
__device__ __forceinline__ unsigned short bf_of(float v) {
    return __bfloat16_as_ushort(__float2bfloat16(v));
}
__device__ __forceinline__ unsigned pack_hi(float a, float b, float& ra, float& rb) {
    unsigned ha = bf_hi(a, ra), hb = bf_hi(b, rb);
    return (hb << 16) | ha;
}
__device__ __forceinline__ unsigned pack_bf(float a, float b) {
    return ((unsigned)bf_of(b) << 16) | bf_of(a);
}
__device__ __forceinline__ float elu1(float v) { return v > 0.f ? v : expm1f(v); }
__device__ __forceinline__ float lrelu(float l) { return l > 0.f ? l : 0.2f * l; }

// ---------------- K1: edge count (first) + weight split + parallel p=W1@a ------
#define W1BLK 128
#define W2BLK 64
#define PBLK  32
__global__ void prep_count(const int* __restrict__ ei,
                           const float* __restrict__ W1, const float* __restrict__ as1,
                           const float* __restrict__ ad1, const float* __restrict__ W2,
                           int edge4Blk) {
    int b = blockIdx.x;
    if (b < edge4Blk) {
        int t = b * blockDim.x + threadIdx.x;
        if (t * 4 >= Ereal) return;
        int4 d4 = ((const int4*)(ei + Ereal))[t];
        int e = t * 4;
        g_epos[e + 0] = atomicAdd(&g_cnt[d4.x], 1);
        g_epos[e + 1] = atomicAdd(&g_cnt[d4.y], 1);
        g_epos[e + 2] = atomicAdd(&g_cnt[d4.z], 1);
        g_epos[e + 3] = atomicAdd(&g_cnt[d4.w], 1);
    } else if (b < edge4Blk + W1BLK) {
        int idx = (b - edge4Blk) * 256 + threadIdx.x;
        int n = idx >> 7, k = idx & 127;
        float v = W1[(size_t)k * D1 + n];
        float r;
        g_w1h[idx] = bf_hi(v, r);
        g_w1l[idx] = bf_of(r);
    } else if (b < edge4Blk + W1BLK + W2BLK) {
        int idx = (b - edge4Blk - W1BLK) * 256 + threadIdx.x;
        int n = idx >> 8, k = idx & 255;
        float v = W2[(size_t)k * D2 + n];
        float r;
        g_w2h[idx] = bf_hi(v, r);
        g_w2l[idx] = bf_of(r);
    } else {
        int w = (b - edge4Blk - W1BLK - W2BLK) * 8 + (threadIdx.x >> 5);
        int lane = threadIdx.x & 31;
        int i = w & 127;
        const float* a = (w < 128) ? as1 : ad1;
        const float* row = W1 + (size_t)i * D1;
        float s = 0.f;
        #pragma unroll
        for (int j = 0; j < 8; j++) s += row[lane + j * 32] * a[lane + j * 32];
        #pragma unroll
        for (int o = 16; o; o >>= 1) s += __shfl_xor_sync(FULL, s, o);
        if (lane == 0) { if (w < 128) g_ps[i] = s; else g_pd[i] = s; }
    }
}

// ---------------- K2: lookback scan + alpha + place (one launch) ----------------
__global__ void scan_alpha_place(const float* __restrict__ x, const int* __restrict__ ei,
                                 int alphaBlk) {
    int b = blockIdx.x;
    if (b < NBLK) {
        __shared__ int wsum[32];
        __shared__ int bpref;
        int tid = threadIdx.x, lane = tid & 31, wid = tid >> 5;
        int i = b * 1024 + tid;
        int v = 0;
        if (i < Nn) {
            v = g_cnt[i] + 1;          // +1 self-loop
            g_cnt[i] = 0;              // restore zero-invariant
        }
        int p = v;
        #pragma unroll
        for (int o = 1; o < 32; o <<= 1) {
            int t = __shfl_up_sync(FULL, p, o);
            if (lane >= o) p += t;
        }
        if (lane == 31) wsum[wid] = p;
        __syncthreads();
        if (wid == 0) {
            int w = wsum[lane];
            #pragma unroll
            for (int o = 1; o < 32; o <<= 1) {
                int t = __shfl_up_sync(FULL, w, o);
                if (lane >= o) w += t;
            }
            wsum[lane] = w;
        }
        __syncthreads();
        if (tid == 0) {
            unsigned total = (unsigned)wsum[31];
            if (b == 0) {
                atomicExch(&g_bsum[0], total | PREF);
                bpref = 0;
            } else {
                atomicExch(&g_bsum[b], total | AGGF);
                int pref = 0;
                int j = b - 1;
                while (j >= 0) {
                    unsigned vv = *(volatile unsigned*)&g_bsum[j];
                    if (vv == 0u) continue;
                    pref += (int)(vv & VMSK);
                    if (vv & PREF) break;
                    j--;
                }
                atomicExch(&g_bsum[b], ((unsigned)pref + total) | PREF);
                bpref = pref;
            }
        }
        __syncthreads();
        int excl = bpref + (wid ? wsum[wid - 1] : 0) + p - v;
        if (i < Nn) {
            g_rowptr[i] = excl;
            g_csr[excl] = i;           // self-loop at slot 0
        }
        if (i == 0) g_rowptr[Nn] = Etot;
        __syncthreads();
        if (tid == 0) {
            __threadfence();
            atomicAdd(&g_scandone, 1);
        }
    } else if (b < NBLK + alphaBlk) {
        int gw = (b - NBLK) * 32 + (threadIdx.x >> 5);
        int lane = threadIdx.x & 31;
        if (gw >= Nn) return;
        float4 v = ((const float4*)(x + (size_t)gw * Cc))[lane];
        float4 p = ((const float4*)g_ps)[lane];
        float4 q = ((const float4*)g_pd)[lane];
        float s1 = v.x * p.x + v.y * p.y + v.z * p.z + v.w * p.w;
        float s2 = v.x * q.x + v.y * q.y + v.z * q.z + v.w * q.w;
        #pragma unroll
        for (int o = 16; o; o >>= 1) {
            s1 += __shfl_xor_sync(FULL, s1, o);
            s2 += __shfl_xor_sync(FULL, s2, o);
        }
        if (lane == 0) { g_as[gw] = s1; g_ad[gw] = s2; }
    } else {
        if (threadIdx.x == 0) {
            while (*(volatile int*)&g_scandone < NBLK) __nanosleep(64);
        }
        __syncthreads();
        int t = (b - NBLK - alphaBlk) * 1024 + threadIdx.x;
        if (t * 4 >= Ereal) return;
        int4 s4 = ((const int4*)ei)[t];
        int4 d4 = ((const int4*)(ei + Ereal))[t];
        int4 p4 = ((const int4*)g_epos)[t];
        g_csr[g_rowptr[d4.x] + 1 + p4.x] = s4.x;
        g_csr[g_rowptr[d4.y] + 1 + p4.y] = s4.y;
        g_csr[g_rowptr[d4.z] + 1 + p4.z] = s4.z;
        g_csr[g_rowptr[d4.w] + 1 + p4.w] = s4.w;
    }
}

// ================= split-bf16 MMA helpers =======================================
#define GS 12

__device__ __forceinline__ void mma_bf16(float (&c)[4], const unsigned* a, const unsigned* b) {
    asm volatile(
        "mma.sync.aligned.m16n8k16.row.col.f32.bf16.bf16.f32 "
        "{%0,%1,%2,%3}, {%4,%5,%6,%7}, {%8,%9}, {%0,%1,%2,%3};\n"
        : "+f"(c[0]), "+f"(c[1]), "+f"(c[2]), "+f"(c[3])
        : "r"(a[0]), "r"(a[1]), "r"(a[2]), "r"(a[3]), "r"(b[0]), "r"(b[1]));
}

// ---------- GEMM1: 256 threads, 128x64 tile, 2 blocks/SM, bias+ELU epilogue -----
// A = g_xh/g_xl [M][128], B = g_w1h/g_w1l [256][128], C -> g_hh/g_hl [M][256].
__global__ void __launch_bounds__(256) gemm1_k(const unsigned short* __restrict__ Ah,
                                               const unsigned short* __restrict__ Al,
                                               const unsigned short* __restrict__ Bh,
                                               const unsigned short* __restrict__ Bl,
                                               unsigned short* __restrict__ Ch,
                                               unsigned short* __restrict__ Cl,
                                               const float* __restrict__ bias,
                                               int M) {
    constexpr int K = Cc;      // 128
    constexpr int N = D1;      // 256
    __shared__ unsigned AsH[128 * GS];
    __shared__ unsigned AsL[128 * GS];
    __shared__ unsigned BsH[64 * GS];
    __shared__ unsigned BsL[64 * GS];

    const int br = blockIdx.y * 128;
    const int bn = blockIdx.x * 64;
    const int tid = threadIdx.x;
    const int lane = tid & 31;
    const int warp = tid >> 5;          // 0..7
    const int wm = (warp >> 1) * 32;    // 4 m-groups
    const int wn = (warp & 1) * 32;     // 2 n-groups

    float acc[2][4][4];
    #pragma unroll
    for (int m = 0; m < 2; m++)
        #pragma unroll
        for (int n = 0; n < 4; n++)
            #pragma unroll
            for (int r = 0; r < 4; r++) acc[m][n][r] = 0.f;

    const int q = lane >> 2;
    const int rr = lane & 3;

    const int aRow0 = tid >> 2,         aC0 = (tid & 3) * 4;
    const int aRow1 = (tid + 256) >> 2;
    const int so0 = aRow0 * GS + (aC0 >> 1);
    const int so1 = aRow1 * GS + (aC0 >> 1);
    const int bRow = tid >> 2;           // 0..63
    const int sob  = bRow * GS + (aC0 >> 1);

    const uint2 Z2 = make_uint2(0u, 0u);
    const bool a0OK = (br + aRow0 < M), a1OK = (br + aRow1 < M);
    uint2 aRh0, aRl0, aRh1, aRl1, bRh, bRl;
    aRh0 = a0OK ? *(const uint2*)(Ah + (size_t)(br + aRow0) * K + aC0) : Z2;
    aRl0 = a0OK ? *(const uint2*)(Al + (size_t)(br + aRow0) * K + aC0) : Z2;
    aRh1 = a1OK ? *(const uint2*)(Ah + (size_t)(br + aRow1) * K + aC0) : Z2;
    aRl1 = a1OK ? *(const uint2*)(Al + (size_t)(br + aRow1) * K + aC0) : Z2;
    bRh = *(const uint2*)(Bh + (size_t)(bn + bRow) * K + aC0);
    bRl = *(const uint2*)(Bl + (size_t)(bn + bRow) * K + aC0);

    for (int k0 = 0; k0 < K; k0 += 16) {
        AsH[so0] = aRh0.x; AsH[so0 + 1] = aRh0.y;
        AsL[so0] = aRl0.x; AsL[so0 + 1] = aRl0.y;
        AsH[so1] = aRh1.x; AsH[so1 + 1] = aRh1.y;
        AsL[so1] = aRl1.x; AsL[so1 + 1] = aRl1.y;
        BsH[sob] = bRh.x; BsH[sob + 1] = bRh.y;
        BsL[sob] = bRl.x; BsL[sob + 1] = bRl.y;
        __syncthreads();

        if (k0 + 16 < K) {
            int kn = k0 + 16;
            aRh0 = a0OK ? *(const uint2*)(Ah + (size_t)(br + aRow0) * K + kn + aC0) : Z2;
            aRl0 = a0OK ? *(const uint2*)(Al + (size_t)(br + aRow0) * K + kn + aC0) : Z2;
            aRh1 = a1OK ? *(const uint2*)(Ah + (size_t)(br + aRow1) * K + kn + aC0) : Z2;
            aRl1 = a1OK ? *(const uint2*)(Al + (size_t)(br + aRow1) * K + kn + aC0) : Z2;
            bRh = *(const uint2*)(Bh + (size_t)(bn + bRow) * K + kn + aC0);
            bRl = *(const uint2*)(Bl + (size_t)(bn + bRow) * K + kn + aC0);
        }

        {
            unsigned ah[2][4], al[2][4], bh[4][2], bl[4][2];
            #pragma unroll
            for (int m = 0; m < 2; m++) {
                int r0 = (wm + m * 16 + q) * GS + rr;
                ah[m][0] = AsH[r0];
                ah[m][1] = AsH[r0 + 8 * GS];
                ah[m][2] = AsH[r0 + 4];
                ah[m][3] = AsH[r0 + 8 * GS + 4];
                al[m][0] = AsL[r0];
                al[m][1] = AsL[r0 + 8 * GS];
                al[m][2] = AsL[r0 + 4];
                al[m][3] = AsL[r0 + 8 * GS + 4];
            }
            #pragma unroll
            for (int n = 0; n < 4; n++) {
                int nb = (wn + n * 8 + q) * GS + rr;
                bh[n][0] = BsH[nb];
                bh[n][1] = BsH[nb + 4];
                bl[n][0] = BsL[nb];
                bl[n][1] = BsL[nb + 4];
            }
            #pragma unroll
            for (int m = 0; m < 2; m++)
                #pragma unroll
                for (int n = 0; n < 4; n++) {
                    mma_bf16(acc[m][n], ah[m], bh[n]);
                    mma_bf16(acc[m][n], ah[m], bl[n]);
                    mma_bf16(acc[m][n], al[m], bh[n]);
                }
        }
        __syncthreads();
    }

    #pragma unroll
    for (int m = 0; m < 2; m++) {
        int row0 = br + wm + m * 16 + q;
        #pragma unroll
        for (int n = 0; n < 4; n++) {
            int col = bn + wn + n * 8 + rr * 2;
            float b0 = bias[col], b1v = bias[col + 1];
            float r0x, r0y, r1x, r1y;
            float v0x = elu1(acc[m][n][0] + b0), v0y = elu1(acc[m][n][1] + b1v);
            float v1x = elu1(acc[m][n][2] + b0), v1y = elu1(acc[m][n][3] + b1v);
            if (row0 < M) {
                *(unsigned*)(Ch + (size_t)row0 * N + col) = pack_hi(v0x, v0y, r0x, r0y);
                *(unsigned*)(Cl + (size_t)row0 * N + col) = pack_bf(r0x, r0y);
            }
            if (row0 + 8 < M) {
                *(unsigned*)(Ch + (size_t)(row0 + 8) * N + col) = pack_hi(v1x, v1y, r1x, r1y);
                *(unsigned*)(Cl + (size_t)(row0 + 8) * N + col) = pack_bf(r1x, r1y);
            }
        }
    }
}

// ---------- GEMM2: 256 threads, 128x64 tile, single buffer, fused alpha ---------
__global__ void __launch_bounds__(256) gemm2_k(const unsigned short* __restrict__ Ah,
                                               const unsigned short* __restrict__ Al,
                                               const unsigned short* __restrict__ Bh,
                                               const unsigned short* __restrict__ Bl,
                                               float* __restrict__ C,
                                               const float* __restrict__ av,
                                               const float* __restrict__ bv,
                                               int M) {
    constexpr int K = D1;   // 256
    constexpr int N = D2;   // 64
    constexpr int WN = 32, NF = 4;
    __shared__ unsigned AsH[128 * GS];
    __shared__ unsigned AsL[128 * GS];
    __shared__ unsigned BsH[64 * GS];
    __shared__ unsigned BsL[64 * GS];

    const int br = blockIdx.y * 128;
    const int tid = threadIdx.x;
    const int lane = tid & 31;
    const int warp = tid >> 5;
    const int wm = (warp >> 1) * 32;
    const int wn = (warp & 1) * WN;

    float acc[2][NF][4];
    #pragma unroll
    for (int m = 0; m < 2; m++)
        #pragma unroll
        for (int n = 0; n < NF; n++)
            #pragma unroll
            for (int r = 0; r < 4; r++) acc[m][n][r] = 0.f;

    const int q = lane >> 2;
    const int rr = lane & 3;

    const int aRow0 = tid >> 2,         aC0 = (tid & 3) * 4;
    const int aRow1 = (tid + 256) >> 2;
    const int so0 = aRow0 * GS + (aC0 >> 1);
    const int so1 = aRow1 * GS + (aC0 >> 1);
    const int bRow = tid >> 2;
    const int sob  = bRow * GS + (aC0 >> 1);

    const uint2 Z2 = make_uint2(0u, 0u);
    const bool a0OK = (br + aRow0 < M), a1OK = (br + aRow1 < M);
    uint2 aRh0, aRl0, aRh1, aRl1, bRh, bRl;
    aRh0 = a0OK ? *(const uint2*)(Ah + (size_t)(br + aRow0) * K + aC0) : Z2;
    aRl0 = a0OK ? *(const uint2*)(Al + (size_t)(br + aRow0) * K + aC0) : Z2;
    aRh1 = a1OK ? *(const uint2*)(Ah + (size_t)(br + aRow1) * K + aC0) : Z2;
    aRl1 = a1OK ? *(const uint2*)(Al + (size_t)(br + aRow1) * K + aC0) : Z2;
    bRh = *(const uint2*)(Bh + (size_t)bRow * K + aC0);
    bRl = *(const uint2*)(Bl + (size_t)bRow * K + aC0);

    for (int k0 = 0; k0 < K; k0 += 16) {
        AsH[so0] = aRh0.x; AsH[so0 + 1] = aRh0.y;
        AsL[so0] = aRl0.x; AsL[so0 + 1] = aRl0.y;
        AsH[so1] = aRh1.x; AsH[so1 + 1] = aRh1.y;
        AsL[so1] = aRl1.x; AsL[so1 + 1] = aRl1.y;
        BsH[sob] = bRh.x; BsH[sob + 1] = bRh.y;
        BsL[sob] = bRl.x; BsL[sob + 1] = bRl.y;
        __syncthreads();

        if (k0 + 16 < K) {
            int kn = k0 + 16;
            aRh0 = a0OK ? *(const uint2*)(Ah + (size_t)(br + aRow0) * K + kn + aC0) : Z2;
            aRl0 = a0OK ? *(const uint2*)(Al + (size_t)(br + aRow0) * K + kn + aC0) : Z2;
            aRh1 = a1OK ? *(const uint2*)(Ah + (size_t)(br + aRow1) * K + kn + aC0) : Z2;
            aRl1 = a1OK ? *(const uint2*)(Al + (size_t)(br + aRow1) * K + kn + aC0) : Z2;
            bRh = *(const uint2*)(Bh + (size_t)bRow * K + kn + aC0);
            bRl = *(const uint2*)(Bl + (size_t)bRow * K + kn + aC0);
        }

        {
            unsigned ah[2][4], al[2][4], bh[NF][2], bl[NF][2];
            #pragma unroll
            for (int m = 0; m < 2; m++) {
                int r0 = (wm + m * 16 + q) * GS + rr;
                ah[m][0] = AsH[r0];
                ah[m][1] = AsH[r0 + 8 * GS];
                ah[m][2] = AsH[r0 + 4];
                ah[m][3] = AsH[r0 + 8 * GS + 4];
                al[m][0] = AsL[r0];
                al[m][1] = AsL[r0 + 8 * GS];
                al[m][2] = AsL[r0 + 4];
                al[m][3] = AsL[r0 + 8 * GS + 4];
            }
            #pragma unroll
            for (int n = 0; n < NF; n++) {
                int nb = (wn + n * 8 + q) * GS + rr;
                bh[n][0] = BsH[nb];
                bh[n][1] = BsH[nb + 4];
                bl[n][0] = BsL[nb];
                bl[n][1] = BsL[nb + 4];
            }
            #pragma unroll
            for (int m = 0; m < 2; m++)
                #pragma unroll
                for (int n = 0; n < NF; n++) {
                    mma_bf16(acc[m][n], ah[m], bh[n]);
                    mma_bf16(acc[m][n], ah[m], bl[n]);
                    mma_bf16(acc[m][n], al[m], bh[n]);
                }
        }
        __syncthreads();
    }

    #pragma unroll
    for (int m = 0; m < 2; m++) {
        int row0 = br + wm + m * 16 + q;
        #pragma unroll
        for (int n = 0; n < NF; n++) {
            int col = wn + n * 8 + rr * 2;
            if (row0 < M)
                *(float2*)(C + (size_t)row0 * N + col) = make_float2(acc[m][n][0], acc[m][n][1]);
            if (row0 + 8 < M)
                *(float2*)(C + (size_t)(row0 + 8) * N + col) = make_float2(acc[m][n][2], acc[m][n][3]);
        }
    }

    // fused alpha: g_as/g_ad = C-row . av/bv (block covers all 64 cols)
    {
        float* sAs = (float*)AsH;
        float* sAd = sAs + 128;
        if (tid < 128) { sAs[tid] = 0.f; sAd[tid] = 0.f; }
        __syncthreads();
        #pragma unroll
        for (int m = 0; m < 2; m++) {
            float pa = 0.f, pd = 0.f, qa = 0.f, qd = 0.f;
            #pragma unroll
            for (int n = 0; n < NF; n++) {
                int col = wn + n * 8 + rr * 2;
                float a0 = av[col], a1 = av[col + 1];
                float d0 = bv[col], d1 = bv[col + 1];
                pa += acc[m][n][0] * a0 + acc[m][n][1] * a1;
                pd += acc[m][n][0] * d0 + acc[m][n][1] * d1;
                qa += acc[m][n][2] * a0 + acc[m][n][3] * a1;
                qd += acc[m][n][2] * d0 + acc[m][n][3] * d1;
            }
            int r = wm + m * 16 + q;
            atomicAdd(&sAs[r], pa);     atomicAdd(&sAd[r], pd);
            atomicAdd(&sAs[r + 8], qa); atomicAdd(&sAd[r + 8], qd);
        }
        __syncthreads();
        if (tid < 128 && br + tid < M) {
            g_as[br + tid] = sAs[tid];
            g_ad[br + tid] = sAd[tid];
        }
    }
}

// ============ shared phase-1: per-warp coef/idx tables in smem ==================
__device__ __forceinline__ void softmax_coefs(
    int gw, int start, int end, const float* __restrict__ asrc, float adn,
    float* wc, int* wi, int lane, float& m_out, float& inv_den_out) {
    int i0 = 0, i1 = 0;
    float l0 = -3.0e38f, l1 = -3.0e38f;
    float m = -3.0e38f, s = 0.f;
    int e = start + lane;
    if (e < end) { i0 = g_csr[e]; l0 = lrelu(asrc[i0] + adn); m = l0; s = 1.f; }
    if (e + 32 < end) {
        i1 = g_csr[e + 32];
        l1 = lrelu(asrc[i1] + adn);
        float mn = fmaxf(m, l1);
        s = s * __expf(m - mn) + __expf(l1 - mn);
        m = mn;
    }
    for (int e2 = e + 64; e2 < end; e2 += 32) {
        float l = lrelu(asrc[g_csr[e2]] + adn);
        float mn = fmaxf(m, l);
        s = s * __expf(m - mn) + __expf(l - mn);
        m = mn;
    }
    #pragma unroll
    for (int off = 16; off; off >>= 1) {
        float mo = __shfl_xor_sync(FULL, m, off);
        float so = __shfl_xor_sync(FULL, s, off);
        float mn = fmaxf(m, mo);
        s = s * __expf(m - mn) + so * __expf(mo - mn);
        m = mn;
    }
    float inv_den = 1.f / s;
    wc[lane]      = __expf(l0 - m) * inv_den;
    wc[lane + 32] = __expf(l1 - m) * inv_den;
    wi[lane]      = i0;
    wi[lane + 32] = i1;
    __syncwarp();
    m_out = m; inv_den_out = inv_den;
}

// ---------------- agg layer 1 (+bsum/scandone reset in block 0) -----------------
__global__ void __launch_bounds__(256, 6) agg128_k(const float* __restrict__ x) {
    __shared__ __align__(16) float scoef[8][64];
    __shared__ __align__(16) int   sidx [8][64];
    if (blockIdx.x == 0) {
        if (threadIdx.x < 64) g_bsum[threadIdx.x] = 0u;
        if (threadIdx.x == 64) g_scandone = 0;
    }
    int gw   = (blockIdx.x * blockDim.x + threadIdx.x) >> 5;
    int lane = threadIdx.x & 31;
    int w    = (threadIdx.x >> 5);
    if (gw >= Nn) return;
    const int start = g_rowptr[gw];
    const int end   = g_rowptr[gw + 1];
    const int deg   = end - start;
    float m, inv_den;
    softmax_coefs(gw, start, end, g_as, g_ad[gw], scoef[w], sidx[w], lane, m, inv_den);
    const int nreg = deg < 64 ? deg : 64;
    const float* wc = scoef[w];
    const int*   wi = sidx[w];

    float4 a0 = make_float4(0.f, 0.f, 0.f, 0.f);
    int j = 0;
    for (; j + 8 <= nreg; j += 8) {
        float4 cA = *(const float4*)&wc[j];
        float4 cB = *(const float4*)&wc[j + 4];
        int4   iA = *(const int4*)&wi[j];
        int4   iB = *(const int4*)&wi[j + 4];
        float4 r0 = ((const float4*)(x + (size_t)iA.x * 128))[lane];
        float4 r1 = ((const float4*)(x + (size_t)iA.y * 128))[lane];
        float4 r2 = ((const float4*)(x + (size_t)iA.z * 128))[lane];
        float4 r3 = ((const float4*)(x + (size_t)iA.w * 128))[lane];
        float4 r4 = ((const float4*)(x + (size_t)iB.x * 128))[lane];
        float4 r5 = ((const float4*)(x + (size_t)iB.y * 128))[lane];
        float4 r6 = ((const float4*)(x + (size_t)iB.z * 128))[lane];
        float4 r7 = ((const float4*)(x + (size_t)iB.w * 128))[lane];
        a0.x += cA.x * r0.x + cA.y * r1.x + cA.z * r2.x + cA.w * r3.x
              + cB.x * r4.x + cB.y * r5.x + cB.z * r6.x + cB.w * r7.x;
        a0.y += cA.x * r0.y + cA.y * r1.y + cA.z * r2.y + cA.w * r3.y
              + cB.x * r4.y + cB.y * r5.y + cB.z * r6.y + cB.w * r7.y;
        a0.z += cA.x * r0.z + cA.y * r1.z + cA.z * r2.z + cA.w * r3.z
              + cB.x * r4.z + cB.y * r5.z + cB.z * r6.z + cB.w * r7.z;
        a0.w += cA.x * r0.w + cA.y * r1.w + cA.z * r2.w + cA.w * r3.w
              + cB.x * r4.w + cB.y * r5.w + cB.z * r6.w + cB.w * r7.w;
    }
    for (; j < nreg; j++) {
        float ca = wc[j];
        int   s0 = wi[j];
        float4 r0 = ((const float4*)(x + (size_t)s0 * 128))[lane];
        a0.x += ca * r0.x; a0.y += ca * r0.y; a0.z += ca * r0.z; a0.w += ca * r0.w;
    }
    for (int e2 = start + 64; e2 < end; e2++) {
        int sn = g_csr[e2];
        float c = __expf(lrelu(g_as[sn] + g_ad[gw]) - m) * inv_den;
        float4 r0 = ((const float4*)(x + (size_t)sn * 128))[lane];
        a0.x += c * r0.x; a0.y += c * r0.y; a0.z += c * r0.z; a0.w += c * r0.w;
    }
    float rx, ry, rz, rw;
    unsigned h01 = pack_hi(a0.x, a0.y, rx, ry);
    unsigned h23 = pack_hi(a0.z, a0.w, rz, rw);
    *(uint2*)(g_xh + (size_t)gw * 128 + lane * 4) = make_uint2(h01, h23);
    *(uint2*)(g_xl + (size_t)gw * 128 + lane * 4) = make_uint2(pack_bf(rx, ry), pack_bf(rz, rw));
}

// ---------------- agg layer 2 (+fused bias/ELU/W3 matvec) -----------------------
__global__ void __launch_bounds__(256, 6) agg64_k(const float* __restrict__ h,
                      float* __restrict__ out, const float* __restrict__ bias,
                      const float* __restrict__ W3, const float* __restrict__ as3,
                      const float* __restrict__ ad3) {
    __shared__ __align__(16) float scoef[8][64];
    __shared__ __align__(16) int   sidx [8][64];
    int gw   = (blockIdx.x * blockDim.x + threadIdx.x) >> 5;
    int lane = threadIdx.x & 31;
    int w    = (threadIdx.x >> 5);
    if (gw >= Nn) return;
    const int start = g_rowptr[gw];
    const int end   = g_rowptr[gw + 1];
    const int deg   = end - start;
    float m, inv_den;
    softmax_coefs(gw, start, end, g_as, g_ad[gw], scoef[w], sidx[w], lane, m, inv_den);
    const int nreg = deg < 64 ? deg : 64;
    const float* wc = scoef[w];
    const int*   wi = sidx[w];

    float2 a = make_float2(0.f, 0.f);
    int j = 0;
    for (; j + 8 <= nreg; j += 8) {
        float4 cA = *(const float4*)&wc[j];
        float4 cB = *(const float4*)&wc[j + 4];
        int4   iA = *(const int4*)&wi[j];
        int4   iB = *(const int4*)&wi[j + 4];
        float2 r0 = ((const float2*)(h + (size_t)iA.x * 64))[lane];
        float2 r1 = ((const float2*)(h + (size_t)iA.y * 64))[lane];
        float2 r2 = ((const float2*)(h + (size_t)iA.z * 64))[lane];
        float2 r3 = ((const float2*)(h + (size_t)iA.w * 64))[lane];
        float2 r4 = ((const float2*)(h + (size_t)iB.x * 64))[lane];
        float2 r5 = ((const float2*)(h + (size_t)iB.y * 64))[lane];
        float2 r6 = ((const float2*)(h + (size_t)iB.z * 64))[lane];
        float2 r7 = ((const float2*)(h + (size_t)iB.w * 64))[lane];
        a.x += cA.x * r0.x + cA.y * r1.x + cA.z * r2.x + cA.w * r3.x
             + cB.x * r4.x + cB.y * r5.x + cB.z * r6.x + cB.w * r7.x;
        a.y += cA.x * r0.y + cA.y * r1.y + cA.z * r2.y + cA.w * r3.y
             + cB.x * r4.y + cB.y * r5.y + cB.z * r6.y + cB.w * r7.y;
    }
    for (; j < nreg; j++) {
        float ca = wc[j];
        int   s0 = wi[j];
        float2 r0 = ((const float2*)(h + (size_t)s0 * 64))[lane];
        a.x += ca * r0.x; a.y += ca * r0.y;
    }
    for (int e2 = start + 64; e2 < end; e2++) {
        int sn = g_csr[e2];
        float c = __expf(lrelu(g_as[sn] + g_ad[gw]) - m) * inv_den;
        float2 r0 = ((const float2*)(h + (size_t)sn * 64))[lane];
        a.x += c * r0.x; a.y += c * r0.y;
    }
    float2 bvv = ((const float2*)bias)[lane];
    a.x = elu1(a.x + bvv.x); a.y = elu1(a.y + bvv.y);
    float2 wv = ((const float2*)W3)[lane];
    float dot = a.x * wv.x + a.y * wv.y;
    #pragma unroll
    for (int off = 16; off; off >>= 1) dot += __shfl_xor_sync(FULL, dot, off);
    if (lane == 0) {
        out[gw]   = dot;
        g_as3[gw] = dot * as3[0];
        g_ad3[gw] = dot * ad3[0];
    }
}

// ---------------- agg layer 3 (scalar) ------------------------------------------
__global__ void agg1_k(const float* __restrict__ h, float* __restrict__ out,
                       const float* __restrict__ bias) {
    int gw   = (blockIdx.x * blockDim.x + threadIdx.x) >> 5;
    int lane = threadIdx.x & 31;
    if (gw >= Nn) return;
    const int start = g_rowptr[gw];
    const int end   = g_rowptr[gw + 1];
    const float adn = g_ad3[gw];

    float m = -3.0e38f, s = 0.f;
    for (int e = start + lane; e < end; e += 32) {
        float l = lrelu(g_as3[g_csr[e]] + adn);
        float mn = fmaxf(m, l);
        s = s * __expf(m - mn) + __expf(l - mn);
        m = mn;
    }
    #pragma unroll
    for (int off = 16; off; off >>= 1) {
        float mo = __shfl_xor_sync(FULL, m, off);
        float so = __shfl_xor_sync(FULL, s, off);
        float mn = fmaxf(m, mo);
        s = s * __expf(m - mn) + so * __expf(mo - mn);
        m = mn;
    }
    const float inv_den = 1.f / s;
    float a = 0.f;
    for (int e = start + lane; e < end; e += 32) {
        int sn = g_csr[e];
        float c = __expf(lrelu(g_as3[sn] + adn) - m) * inv_den;
        a += c * h[sn];
    }
    #pragma unroll
    for (int off = 16; off; off >>= 1) a += __shfl_xor_sync(FULL, a, off);
    if (lane == 0) out[gw] = a + bias[0];
}

// =============================== launcher ======================================
extern "C" void kernel_launch(void* const* d_in, const int* in_sizes, int n_in,
                              void* d_out, int out_size) {
    const float* x  = (const float*)d_in[0];
    const int*   ei = (const int*)d_in[1];
    const float *W1 = (const float*)d_in[2],  *as1 = (const float*)d_in[3],
                *ad1 = (const float*)d_in[4], *b1  = (const float*)d_in[5];
    const float *W2 = (const float*)d_in[6],  *as2 = (const float*)d_in[7],
                *ad2 = (const float*)d_in[8], *b2  = (const float*)d_in[9];
    const float *W3 = (const float*)d_in[10], *as3 = (const float*)d_in[11],
                *ad3 = (const float*)d_in[12], *b3 = (const float*)d_in[13];
    float* out = (float*)d_out;

    unsigned short *pxh, *pxl, *phh, *phl, *pw1h, *pw1l, *pw2h, *pw2l;
    float *po, *py;
    cudaGetSymbolAddress((void**)&pxh, g_xh);
    cudaGetSymbolAddress((void**)&pxl, g_xl);
    cudaGetSymbolAddress((void**)&phh, g_hh);
    cudaGetSymbolAddress((void**)&phl, g_hl);
    cudaGetSymbolAddress((void**)&pw1h, g_w1h);
    cudaGetSymbolAddress((void**)&pw1l, g_w1l);
    cudaGetSymbolAddress((void**)&pw2h, g_w2h);
    cudaGetSymbolAddress((void**)&pw2l, g_w2l);
    cudaGetSymbolAddress((void**)&po, g_o);
    cudaGetSymbolAddress((void**)&py, g_y);

    const int TB = 256;
    const int warpNodeBlk = (Nn * 32 + TB - 1) / TB;
    const int edge4Blk    = (Ereal / 4 + TB - 1) / TB;
    const int alphaBlk    = (Nn + 31) / 32;
    const int place1024   = (Ereal / 4 + 1023) / 1024;
    const int mRows = (Nn + 127) / 128;

    prep_count<<<edge4Blk + W1BLK + W2BLK + PBLK, TB>>>(ei, W1, as1, ad1, W2, edge4Blk);
    scan_alpha_place<<<NBLK + alphaBlk + place1024, 1024>>>(x, ei, alphaBlk);

    // ---- layer 1 (aggregate-then-transform): 128 -> 256 ----
    agg128_k<<<warpNodeBlk, TB>>>(x);
    {
        dim3 grid(D1 / 64, mRows);   // BN=64, 2 blocks/SM
        gemm1_k<<<grid, 256>>>(pxh, pxl, pw1h, pw1l, phh, phl, b1, Nn);
    }
    // ---- layer 2: 256 -> 64 ----
    {
        dim3 grid(1, mRows);
        gemm2_k<<<grid, 256>>>(phh, phl, pw2h, pw2l, po, as2, ad2, Nn);
        agg64_k<<<warpNodeBlk, TB>>>(po, py, b2, W3, as3, ad3);
    }
    // ---- layer 3: 64 -> 1 ----
    agg1_k<<<warpNodeBlk, TB>>>(py, out, b3);
}

// round 17
// speedup vs baseline: 1.0384x; 1.0268x over previous
#include <cuda_runtime.h>
#include <cuda_bf16.h>
#include <math.h>

#define Nn     50000
#define Cc     128
#define D1     256
#define D2     64
#define Ereal  800000
#define Etot   (Ereal + Nn)
#define FULL   0xFFFFFFFFu
#define NBLK   ((Nn + 1023) / 1024)
#define AGGF   (1u << 30)
#define PREF   (1u << 31)
#define VMSK   0x3FFFFFFFu

// ---------------- scratch ------------------------------------------------------
__device__ unsigned short g_xh[(size_t)Nn * Cc];
__device__ unsigned short g_xl[(size_t)Nn * Cc];
__device__ unsigned short g_hh[(size_t)Nn * D1];
__device__ unsigned short g_hl[(size_t)Nn * D1];
__device__ unsigned short g_w1h[D1 * Cc];
__device__ unsigned short g_w1l[D1 * Cc];
__device__ unsigned short g_w2h[D2 * D1];
__device__ unsigned short g_w2l[D2 * D1];
__device__ float g_o [(size_t)Nn * D2];
__device__ float g_y [Nn];
__device__ float g_as[Nn];
__device__ float g_ad[Nn];
__device__ float g_as3[Nn];
__device__ float g_ad3[Nn];
__device__ float g_ps[Cc];
__device__ float g_pd[Cc];
__device__ int   g_cnt [Nn];      // zero-invariant (scan resets)
__device__ int   g_epos[Ereal];
__device__ int   g_rowptr[Nn + 1];
__device__ int   g_csr[Etot];
__device__ unsigned g_bsum[64];   // lookback flags; reset by agg128 blk0
__device__ int   g_scandone;      // scan completion counter; reset by agg128 blk0

__device__ __forceinline__ unsigned short bf_hi(float v, float& r) {
    __nv_bfloat16 h = __float2bfloat16(v);
    r = v - __bfloat162float(h);
    return __bfloat16_as_ushort(h);
}
__device__ __forceinline__ unsigned short bf_of(float v) {
    return __bfloat16_as_ushort(__float2bfloat16(v));
}
__device__ __forceinline__ unsigned pack_hi(float a, float b, float& ra, float& rb) {
    unsigned ha = bf_hi(a, ra), hb = bf_hi(b, rb);
    return (hb << 16) | ha;
}
__device__ __forceinline__ unsigned pack_bf(float a, float b) {
    return ((unsigned)bf_of(b) << 16) | bf_of(a);
}
__device__ __forceinline__ float elu1(float v) { return v > 0.f ? v : expm1f(v); }
__device__ __forceinline__ float lrelu(float l) { return l > 0.f ? l : 0.2f * l; }

// ---------------- K1: edge count (first) + weight split + parallel p=W1@a ------
#define W1BLK 128
#define W2BLK 64
#define PBLK  32
__global__ void prep_count(const int* __restrict__ ei,
                           const float* __restrict__ W1, const float* __restrict__ as1,
                           const float* __restrict__ ad1, const float* __restrict__ W2,
                           int edge4Blk) {
    int b = blockIdx.x;
    if (b < edge4Blk) {
        int t = b * blockDim.x + threadIdx.x;
        if (t * 4 >= Ereal) return;
        int4 d4 = ((const int4*)(ei + Ereal))[t];
        int e = t * 4;
        g_epos[e + 0] = atomicAdd(&g_cnt[d4.x], 1);
        g_epos[e + 1] = atomicAdd(&g_cnt[d4.y], 1);
        g_epos[e + 2] = atomicAdd(&g_cnt[d4.z], 1);
        g_epos[e + 3] = atomicAdd(&g_cnt[d4.w], 1);
    } else if (b < edge4Blk + W1BLK) {
        int idx = (b - edge4Blk) * 256 + threadIdx.x;
        int n = idx >> 7, k = idx & 127;
        float v = W1[(size_t)k * D1 + n];
        float r;
        g_w1h[idx] = bf_hi(v, r);
        g_w1l[idx] = bf_of(r);
    } else if (b < edge4Blk + W1BLK + W2BLK) {
        int idx = (b - edge4Blk - W1BLK) * 256 + threadIdx.x;
        int n = idx >> 8, k = idx & 255;
        float v = W2[(size_t)k * D2 + n];
        float r;
        g_w2h[idx] = bf_hi(v, r);
        g_w2l[idx] = bf_of(r);
    } else {
        int w = (b - edge4Blk - W1BLK - W2BLK) * 8 + (threadIdx.x >> 5);
        int lane = threadIdx.x & 31;
        int i = w & 127;
        const float* a = (w < 128) ? as1 : ad1;
        const float* row = W1 + (size_t)i * D1;
        float s = 0.f;
        #pragma unroll
        for (int j = 0; j < 8; j++) s += row[lane + j * 32] * a[lane + j * 32];
        #pragma unroll
        for (int o = 16; o; o >>= 1) s += __shfl_xor_sync(FULL, s, o);
        if (lane == 0) { if (w < 128) g_ps[i] = s; else g_pd[i] = s; }
    }
}

// ---------------- K2: lookback scan + alpha + place (one launch) ----------------
__global__ void scan_alpha_place(const float* __restrict__ x, const int* __restrict__ ei,
                                 int alphaBlk) {
    int b = blockIdx.x;
    if (b < NBLK) {
        __shared__ int wsum[32];
        __shared__ int bpref;
        int tid = threadIdx.x, lane = tid & 31, wid = tid >> 5;
        int i = b * 1024 + tid;
        int v = 0;
        if (i < Nn) {
            v = g_cnt[i] + 1;          // +1 self-loop
            g_cnt[i] = 0;              // restore zero-invariant
        }
        int p = v;
        #pragma unroll
        for (int o = 1; o < 32; o <<= 1) {
            int t = __shfl_up_sync(FULL, p, o);
            if (lane >= o) p += t;
        }
        if (lane == 31) wsum[wid] = p;
        __syncthreads();
        if (wid == 0) {
            int w = wsum[lane];
            #pragma unroll
            for (int o = 1; o < 32; o <<= 1) {
                int t = __shfl_up_sync(FULL, w, o);
                if (lane >= o) w += t;
            }
            wsum[lane] = w;
        }
        __syncthreads();
        if (tid == 0) {
            unsigned total = (unsigned)wsum[31];
            if (b == 0) {
                atomicExch(&g_bsum[0], total | PREF);
                bpref = 0;
            } else {
                atomicExch(&g_bsum[b], total | AGGF);
                int pref = 0;
                int j = b - 1;
                while (j >= 0) {
                    unsigned vv = *(volatile unsigned*)&g_bsum[j];
                    if (vv == 0u) continue;
                    pref += (int)(vv & VMSK);
                    if (vv & PREF) break;
                    j--;
                }
                atomicExch(&g_bsum[b], ((unsigned)pref + total) | PREF);
                bpref = pref;
            }
        }
        __syncthreads();
        int excl = bpref + (wid ? wsum[wid - 1] : 0) + p - v;
        if (i < Nn) {
            g_rowptr[i] = excl;
            g_csr[excl] = i;           // self-loop at slot 0
        }
        if (i == 0) g_rowptr[Nn] = Etot;
        __syncthreads();
        if (tid == 0) {
            __threadfence();
            atomicAdd(&g_scandone, 1);
        }
    } else if (b < NBLK + alphaBlk) {
        int gw = (b - NBLK) * 32 + (threadIdx.x >> 5);
        int lane = threadIdx.x & 31;
        if (gw >= Nn) return;
        float4 v = ((const float4*)(x + (size_t)gw * Cc))[lane];
        float4 p = ((const float4*)g_ps)[lane];
        float4 q = ((const float4*)g_pd)[lane];
        float s1 = v.x * p.x + v.y * p.y + v.z * p.z + v.w * p.w;
        float s2 = v.x * q.x + v.y * q.y + v.z * q.z + v.w * q.w;
        #pragma unroll
        for (int o = 16; o; o >>= 1) {
            s1 += __shfl_xor_sync(FULL, s1, o);
            s2 += __shfl_xor_sync(FULL, s2, o);
        }
        if (lane == 0) { g_as[gw] = s1; g_ad[gw] = s2; }
    } else {
        if (threadIdx.x == 0) {
            while (*(volatile int*)&g_scandone < NBLK) __nanosleep(64);
        }
        __syncthreads();
        int t = (b - NBLK - alphaBlk) * 1024 + threadIdx.x;
        if (t * 4 >= Ereal) return;
        int4 s4 = ((const int4*)ei)[t];
        int4 d4 = ((const int4*)(ei + Ereal))[t];
        int4 p4 = ((const int4*)g_epos)[t];
        g_csr[g_rowptr[d4.x] + 1 + p4.x] = s4.x;
        g_csr[g_rowptr[d4.y] + 1 + p4.y] = s4.y;
        g_csr[g_rowptr[d4.z] + 1 + p4.z] = s4.z;
        g_csr[g_rowptr[d4.w] + 1 + p4.w] = s4.w;
    }
}

// ================= split-bf16 MMA helpers =======================================
#define GS 12   // smem row stride in uints (48 B) — conflict-free for ldmatrix

__device__ __forceinline__ void mma_bf16(float (&c)[4], const unsigned* a, const unsigned* b) {
    asm volatile(
        "mma.sync.aligned.m16n8k16.row.col.f32.bf16.bf16.f32 "
        "{%0,%1,%2,%3}, {%4,%5,%6,%7}, {%8,%9}, {%0,%1,%2,%3};\n"
        : "+f"(c[0]), "+f"(c[1]), "+f"(c[2]), "+f"(c[3])
        : "r"(a[0]), "r"(a[1]), "r"(a[2]), "r"(a[3]), "r"(b[0]), "r"(b[1]));
}
__device__ __forceinline__ void ldsm4(unsigned* d, unsigned addr) {
    asm volatile("ldmatrix.sync.aligned.m8n8.x4.shared.b16 {%0,%1,%2,%3}, [%4];"
        : "=r"(d[0]), "=r"(d[1]), "=r"(d[2]), "=r"(d[3]) : "r"(addr));
}

// A-frag lane byte-offset (rows base..base+15, k-lo|k-hi halves)
__device__ __forceinline__ int a_frag_off(int baseRow, int lane) {
    return (baseRow + (lane & 15)) * (GS * 4) + ((lane & 16) ? 16 : 0);
}
// B-frag lane byte-offset (2 n-groups of 8 rows from baseRow, k-lo|k-hi)
__device__ __forceinline__ int b_frag_off(int baseRow, int lane) {
    int row = baseRow + (lane & 7) + ((lane & 16) ? 8 : 0);
    return row * (GS * 4) + ((lane & 8) ? 16 : 0);
}

// ---------- GEMM1: 256 threads, 128x64 tile, ldmatrix frags, bias+ELU epilogue --
__global__ void __launch_bounds__(256) gemm1_k(const unsigned short* __restrict__ Ah,
                                               const unsigned short* __restrict__ Al,
                                               const unsigned short* __restrict__ Bh,
                                               const unsigned short* __restrict__ Bl,
                                               unsigned short* __restrict__ Ch,
                                               unsigned short* __restrict__ Cl,
                                               const float* __restrict__ bias,
                                               int M) {
    constexpr int K = Cc;      // 128
    constexpr int N = D1;      // 256
    __shared__ unsigned AsH[128 * GS];
    __shared__ unsigned AsL[128 * GS];
    __shared__ unsigned BsH[64 * GS];
    __shared__ unsigned BsL[64 * GS];

    const int br = blockIdx.y * 128;
    const int bn = blockIdx.x * 64;
    const int tid = threadIdx.x;
    const int lane = tid & 31;
    const int warp = tid >> 5;          // 0..7
    const int wm = (warp >> 1) * 32;
    const int wn = (warp & 1) * 32;

    float acc[2][4][4];
    #pragma unroll
    for (int m = 0; m < 2; m++)
        #pragma unroll
        for (int n = 0; n < 4; n++)
            #pragma unroll
            for (int r = 0; r < 4; r++) acc[m][n][r] = 0.f;

    const int q = lane >> 2;
    const int rr = lane & 3;

    const int aRow0 = tid >> 2,         aC0 = (tid & 3) * 4;
    const int aRow1 = (tid + 256) >> 2;
    const int so0 = aRow0 * GS + (aC0 >> 1);
    const int so1 = aRow1 * GS + (aC0 >> 1);
    const int bRow = tid >> 2;           // 0..63
    const int sob  = bRow * GS + (aC0 >> 1);

    // ldmatrix shared-space bases + lane offsets
    const unsigned baH = (unsigned)__cvta_generic_to_shared(AsH);
    const unsigned baL = (unsigned)__cvta_generic_to_shared(AsL);
    const unsigned bbH = (unsigned)__cvta_generic_to_shared(BsH);
    const unsigned bbL = (unsigned)__cvta_generic_to_shared(BsL);
    const int af0 = a_frag_off(wm, lane);
    const int af1 = a_frag_off(wm + 16, lane);
    const int bf0 = b_frag_off(wn, lane);
    const int bf1 = b_frag_off(wn + 16, lane);

    const uint2 Z2 = make_uint2(0u, 0u);
    const bool a0OK = (br + aRow0 < M), a1OK = (br + aRow1 < M);
    uint2 aRh0, aRl0, aRh1, aRl1, bRh, bRl;
    aRh0 = a0OK ? *(const uint2*)(Ah + (size_t)(br + aRow0) * K + aC0) : Z2;
    aRl0 = a0OK ? *(const uint2*)(Al + (size_t)(br + aRow0) * K + aC0) : Z2;
    aRh1 = a1OK ? *(const uint2*)(Ah + (size_t)(br + aRow1) * K + aC0) : Z2;
    aRl1 = a1OK ? *(const uint2*)(Al + (size_t)(br + aRow1) * K + aC0) : Z2;
    bRh = *(const uint2*)(Bh + (size_t)(bn + bRow) * K + aC0);
    bRl = *(const uint2*)(Bl + (size_t)(bn + bRow) * K + aC0);

    for (int k0 = 0; k0 < K; k0 += 16) {
        AsH[so0] = aRh0.x; AsH[so0 + 1] = aRh0.y;
        AsL[so0] = aRl0.x; AsL[so0 + 1] = aRl0.y;
        AsH[so1] = aRh1.x; AsH[so1 + 1] = aRh1.y;
        AsL[so1] = aRl1.x; AsL[so1 + 1] = aRl1.y;
        BsH[sob] = bRh.x; BsH[sob + 1] = bRh.y;
        BsL[sob] = bRl.x; BsL[sob + 1] = bRl.y;
        __syncthreads();

        if (k0 + 16 < K) {
            int kn = k0 + 16;
            aRh0 = a0OK ? *(const uint2*)(Ah + (size_t)(br + aRow0) * K + kn + aC0) : Z2;
            aRl0 = a0OK ? *(const uint2*)(Al + (size_t)(br + aRow0) * K + kn + aC0) : Z2;
            aRh1 = a1OK ? *(const uint2*)(Ah + (size_t)(br + aRow1) * K + kn + aC0) : Z2;
            aRl1 = a1OK ? *(const uint2*)(Al + (size_t)(br + aRow1) * K + kn + aC0) : Z2;
            bRh = *(const uint2*)(Bh + (size_t)(bn + bRow) * K + kn + aC0);
            bRl = *(const uint2*)(Bl + (size_t)(bn + bRow) * K + kn + aC0);
        }

        {
            unsigned ah[2][4], al[2][4], bh[4][2], bl[4][2];
            ldsm4(ah[0], baH + af0);
            ldsm4(ah[1], baH + af1);
            ldsm4(al[0], baL + af0);
            ldsm4(al[1], baL + af1);
            ldsm4(&bh[0][0], bbH + bf0);
            ldsm4(&bh[2][0], bbH + bf1);
            ldsm4(&bl[0][0], bbL + bf0);
            ldsm4(&bl[2][0], bbL + bf1);
            #pragma unroll
            for (int m = 0; m < 2; m++)
                #pragma unroll
                for (int n = 0; n < 4; n++) {
                    mma_bf16(acc[m][n], ah[m], bh[n]);
                    mma_bf16(acc[m][n], ah[m], bl[n]);
                    mma_bf16(acc[m][n], al[m], bh[n]);
                }
        }
        __syncthreads();
    }

    #pragma unroll
    for (int m = 0; m < 2; m++) {
        int row0 = br + wm + m * 16 + q;
        #pragma unroll
        for (int n = 0; n < 4; n++) {
            int col = bn + wn + n * 8 + rr * 2;
            float b0 = bias[col], b1v = bias[col + 1];
            float r0x, r0y, r1x, r1y;
            float v0x = elu1(acc[m][n][0] + b0), v0y = elu1(acc[m][n][1] + b1v);
            float v1x = elu1(acc[m][n][2] + b0), v1y = elu1(acc[m][n][3] + b1v);
            if (row0 < M) {
                *(unsigned*)(Ch + (size_t)row0 * N + col) = pack_hi(v0x, v0y, r0x, r0y);
                *(unsigned*)(Cl + (size_t)row0 * N + col) = pack_bf(r0x, r0y);
            }
            if (row0 + 8 < M) {
                *(unsigned*)(Ch + (size_t)(row0 + 8) * N + col) = pack_hi(v1x, v1y, r1x, r1y);
                *(unsigned*)(Cl + (size_t)(row0 + 8) * N + col) = pack_bf(r1x, r1y);
            }
        }
    }
}

// ---------- GEMM2: 256 threads, 128x64 tile, ldmatrix frags, fused alpha --------
__global__ void __launch_bounds__(256) gemm2_k(const unsigned short* __restrict__ Ah,
                                               const unsigned short* __restrict__ Al,
                                               const unsigned short* __restrict__ Bh,
                                               const unsigned short* __restrict__ Bl,
                                               float* __restrict__ C,
                                               const float* __restrict__ av,
                                               const float* __restrict__ bv,
                                               int M) {
    constexpr int K = D1;   // 256
    constexpr int N = D2;   // 64
    constexpr int NF = 4;
    __shared__ unsigned AsH[128 * GS];
    __shared__ unsigned AsL[128 * GS];
    __shared__ unsigned BsH[64 * GS];
    __shared__ unsigned BsL[64 * GS];

    const int br = blockIdx.y * 128;
    const int tid = threadIdx.x;
    const int lane = tid & 31;
    const int warp = tid >> 5;
    const int wm = (warp >> 1) * 32;
    const int wn = (warp & 1) * 32;

    float acc[2][NF][4];
    #pragma unroll
    for (int m = 0; m < 2; m++)
        #pragma unroll
        for (int n = 0; n < NF; n++)
            #pragma unroll
            for (int r = 0; r < 4; r++) acc[m][n][r] = 0.f;

    const int q = lane >> 2;
    const int rr = lane & 3;

    const int aRow0 = tid >> 2,         aC0 = (tid & 3) * 4;
    const int aRow1 = (tid + 256) >> 2;
    const int so0 = aRow0 * GS + (aC0 >> 1);
    const int so1 = aRow1 * GS + (aC0 >> 1);
    const int bRow = tid >> 2;
    const int sob  = bRow * GS + (aC0 >> 1);

    const unsigned baH = (unsigned)__cvta_generic_to_shared(AsH);
    const unsigned baL = (unsigned)__cvta_generic_to_shared(AsL);
    const unsigned bbH = (unsigned)__cvta_generic_to_shared(BsH);
    const unsigned bbL = (unsigned)__cvta_generic_to_shared(BsL);
    const int af0 = a_frag_off(wm, lane);
    const int af1 = a_frag_off(wm + 16, lane);
    const int bf0 = b_frag_off(wn, lane);
    const int bf1 = b_frag_off(wn + 16, lane);

    const uint2 Z2 = make_uint2(0u, 0u);
    const bool a0OK = (br + aRow0 < M), a1OK = (br + aRow1 < M);
    uint2 aRh0, aRl0, aRh1, aRl1, bRh, bRl;
    aRh0 = a0OK ? *(const uint2*)(Ah + (size_t)(br + aRow0) * K + aC0) : Z2;
    aRl0 = a0OK ? *(const uint2*)(Al + (size_t)(br + aRow0) * K + aC0) : Z2;
    aRh1 = a1OK ? *(const uint2*)(Ah + (size_t)(br + aRow1) * K + aC0) : Z2;
    aRl1 = a1OK ? *(const uint2*)(Al + (size_t)(br + aRow1) * K + aC0) : Z2;
    bRh = *(const uint2*)(Bh + (size_t)bRow * K + aC0);
    bRl = *(const uint2*)(Bl + (size_t)bRow * K + aC0);

    for (int k0 = 0; k0 < K; k0 += 16) {
        AsH[so0] = aRh0.x; AsH[so0 + 1] = aRh0.y;
        AsL[so0] = aRl0.x; AsL[so0 + 1] = aRl0.y;
        AsH[so1] = aRh1.x; AsH[so1 + 1] = aRh1.y;
        AsL[so1] = aRl1.x; AsL[so1 + 1] = aRl1.y;
        BsH[sob] = bRh.x; BsH[sob + 1] = bRh.y;
        BsL[sob] = bRl.x; BsL[sob + 1] = bRl.y;
        __syncthreads();

        if (k0 + 16 < K) {
            int kn = k0 + 16;
            aRh0 = a0OK ? *(const uint2*)(Ah + (size_t)(br + aRow0) * K + kn + aC0) : Z2;
            aRl0 = a0OK ? *(const uint2*)(Al + (size_t)(br + aRow0) * K + kn + aC0) : Z2;
            aRh1 = a1OK ? *(const uint2*)(Ah + (size_t)(br + aRow1) * K + kn + aC0) : Z2;
            aRl1 = a1OK ? *(const uint2*)(Al + (size_t)(br + aRow1) * K + kn + aC0) : Z2;
            bRh = *(const uint2*)(Bh + (size_t)bRow * K + kn + aC0);
            bRl = *(const uint2*)(Bl + (size_t)bRow * K + kn + aC0);
        }

        {
            unsigned ah[2][4], al[2][4], bh[NF][2], bl[NF][2];
            ldsm4(ah[0], baH + af0);
            ldsm4(ah[1], baH + af1);
            ldsm4(al[0], baL + af0);
            ldsm4(al[1], baL + af1);
            ldsm4(&bh[0][0], bbH + bf0);
            ldsm4(&bh[2][0], bbH + bf1);
            ldsm4(&bl[0][0], bbL + bf0);
            ldsm4(&bl[2][0], bbL + bf1);
            #pragma unroll
            for (int m = 0; m < 2; m++)
                #pragma unroll
                for (int n = 0; n < NF; n++) {
                    mma_bf16(acc[m][n], ah[m], bh[n]);
                    mma_bf16(acc[m][n], ah[m], bl[n]);
                    mma_bf16(acc[m][n], al[m], bh[n]);
                }
        }
        __syncthreads();
    }

    #pragma unroll
    for (int m = 0; m < 2; m++) {
        int row0 = br + wm + m * 16 + q;
        #pragma unroll
        for (int n = 0; n < NF; n++) {
            int col = wn + n * 8 + rr * 2;
            if (row0 < M)
                *(float2*)(C + (size_t)row0 * N + col) = make_float2(acc[m][n][0], acc[m][n][1]);
            if (row0 + 8 < M)
                *(float2*)(C + (size_t)(row0 + 8) * N + col) = make_float2(acc[m][n][2], acc[m][n][3]);
        }
    }

    // fused alpha: g_as/g_ad = C-row . av/bv (block covers all 64 cols)
    {
        float* sAs = (float*)AsH;
        float* sAd = sAs + 128;
        if (tid < 128) { sAs[tid] = 0.f; sAd[tid] = 0.f; }
        __syncthreads();
        #pragma unroll
        for (int m = 0; m < 2; m++) {
            float pa = 0.f, pd = 0.f, qa = 0.f, qd = 0.f;
            #pragma unroll
            for (int n = 0; n < NF; n++) {
                int col = wn + n * 8 + rr * 2;
                float a0 = av[col], a1 = av[col + 1];
                float d0 = bv[col], d1 = bv[col + 1];
                pa += acc[m][n][0] * a0 + acc[m][n][1] * a1;
                pd += acc[m][n][0] * d0 + acc[m][n][1] * d1;
                qa += acc[m][n][2] * a0 + acc[m][n][3] * a1;
                qd += acc[m][n][2] * d0 + acc[m][n][3] * d1;
            }
            int r = wm + m * 16 + q;
            atomicAdd(&sAs[r], pa);     atomicAdd(&sAd[r], pd);
            atomicAdd(&sAs[r + 8], qa); atomicAdd(&sAd[r + 8], qd);
        }
        __syncthreads();
        if (tid < 128 && br + tid < M) {
            g_as[br + tid] = sAs[tid];
            g_ad[br + tid] = sAd[tid];
        }
    }
}

// ============ shared phase-1: per-warp coef/idx tables in smem ==================
__device__ __forceinline__ void softmax_coefs(
    int gw, int start, int end, const float* __restrict__ asrc, float adn,
    float* wc, int* wi, int lane, float& m_out, float& inv_den_out) {
    int i0 = 0, i1 = 0;
    float l0 = -3.0e38f, l1 = -3.0e38f;
    float m = -3.0e38f, s = 0.f;
    int e = start + lane;
    if (e < end) { i0 = g_csr[e]; l0 = lrelu(asrc[i0] + adn); m = l0; s = 1.f; }
    if (e + 32 < end) {
        i1 = g_csr[e + 32];
        l1 = lrelu(asrc[i1] + adn);
        float mn = fmaxf(m, l1);
        s = s * __expf(m - mn) + __expf(l1 - mn);
        m = mn;
    }
    for (int e2 = e + 64; e2 < end; e2 += 32) {
        float l = lrelu(asrc[g_csr[e2]] + adn);
        float mn = fmaxf(m, l);
        s = s * __expf(m - mn) + __expf(l - mn);
        m = mn;
    }
    #pragma unroll
    for (int off = 16; off; off >>= 1) {
        float mo = __shfl_xor_sync(FULL, m, off);
        float so = __shfl_xor_sync(FULL, s, off);
        float mn = fmaxf(m, mo);
        s = s * __expf(m - mn) + so * __expf(mo - mn);
        m = mn;
    }
    float inv_den = 1.f / s;
    wc[lane]      = __expf(l0 - m) * inv_den;
    wc[lane + 32] = __expf(l1 - m) * inv_den;
    wi[lane]      = i0;
    wi[lane + 32] = i1;
    __syncwarp();
    m_out = m; inv_den_out = inv_den;
}

// ---------------- agg layer 1 (+bsum/scandone reset in block 0) -----------------
__global__ void __launch_bounds__(256, 6) agg128_k(const float* __restrict__ x) {
    __shared__ __align__(16) float scoef[8][64];
    __shared__ __align__(16) int   sidx [8][64];
    if (blockIdx.x == 0) {
        if (threadIdx.x < 64) g_bsum[threadIdx.x] = 0u;
        if (threadIdx.x == 64) g_scandone = 0;
    }
    int gw   = (blockIdx.x * blockDim.x + threadIdx.x) >> 5;
    int lane = threadIdx.x & 31;
    int w    = (threadIdx.x >> 5);
    if (gw >= Nn) return;
    const int start = g_rowptr[gw];
    const int end   = g_rowptr[gw + 1];
    const int deg   = end - start;
    float m, inv_den;
    softmax_coefs(gw, start, end, g_as, g_ad[gw], scoef[w], sidx[w], lane, m, inv_den);
    const int nreg = deg < 64 ? deg : 64;
    const float* wc = scoef[w];
    const int*   wi = sidx[w];

    float4 a0 = make_float4(0.f, 0.f, 0.f, 0.f);
    int j = 0;
    for (; j + 8 <= nreg; j += 8) {
        float4 cA = *(const float4*)&wc[j];
        float4 cB = *(const float4*)&wc[j + 4];
        int4   iA = *(const int4*)&wi[j];
        int4   iB = *(const int4*)&wi[j + 4];
        float4 r0 = ((const float4*)(x + (size_t)iA.x * 128))[lane];
        float4 r1 = ((const float4*)(x + (size_t)iA.y * 128))[lane];
        float4 r2 = ((const float4*)(x + (size_t)iA.z * 128))[lane];
        float4 r3 = ((const float4*)(x + (size_t)iA.w * 128))[lane];
        float4 r4 = ((const float4*)(x + (size_t)iB.x * 128))[lane];
        float4 r5 = ((const float4*)(x + (size_t)iB.y * 128))[lane];
        float4 r6 = ((const float4*)(x + (size_t)iB.z * 128))[lane];
        float4 r7 = ((const float4*)(x + (size_t)iB.w * 128))[lane];
        a0.x += cA.x * r0.x + cA.y * r1.x + cA.z * r2.x + cA.w * r3.x
              + cB.x * r4.x + cB.y * r5.x + cB.z * r6.x + cB.w * r7.x;
        a0.y += cA.x * r0.y + cA.y * r1.y + cA.z * r2.y + cA.w * r3.y
              + cB.x * r4.y + cB.y * r5.y + cB.z * r6.y + cB.w * r7.y;
        a0.z += cA.x * r0.z + cA.y * r1.z + cA.z * r2.z + cA.w * r3.z
              + cB.x * r4.z + cB.y * r5.z + cB.z * r6.z + cB.w * r7.z;
        a0.w += cA.x * r0.w + cA.y * r1.w + cA.z * r2.w + cA.w * r3.w
              + cB.x * r4.w + cB.y * r5.w + cB.z * r6.w + cB.w * r7.w;
    }
    for (; j < nreg; j++) {
        float ca = wc[j];
        int   s0 = wi[j];
        float4 r0 = ((const float4*)(x + (size_t)s0 * 128))[lane];
        a0.x += ca * r0.x; a0.y += ca * r0.y; a0.z += ca * r0.z; a0.w += ca * r0.w;
    }
    for (int e2 = start + 64; e2 < end; e2++) {
        int sn = g_csr[e2];
        float c = __expf(lrelu(g_as[sn] + g_ad[gw]) - m) * inv_den;
        float4 r0 = ((const float4*)(x + (size_t)sn * 128))[lane];
        a0.x += c * r0.x; a0.y += c * r0.y; a0.z += c * r0.z; a0.w += c * r0.w;
    }
    float rx, ry, rz, rw;
    unsigned h01 = pack_hi(a0.x, a0.y, rx, ry);
    unsigned h23 = pack_hi(a0.z, a0.w, rz, rw);
    *(uint2*)(g_xh + (size_t)gw * 128 + lane * 4) = make_uint2(h01, h23);
    *(uint2*)(g_xl + (size_t)gw * 128 + lane * 4) = make_uint2(pack_bf(rx, ry), pack_bf(rz, rw));
}

// ---------------- agg layer 2 (+fused bias/ELU/W3 matvec) -----------------------
__global__ void __launch_bounds__(256, 6) agg64_k(const float* __restrict__ h,
                      float* __restrict__ out, const float* __restrict__ bias,
                      const float* __restrict__ W3, const float* __restrict__ as3,
                      const float* __restrict__ ad3) {
    __shared__ __align__(16) float scoef[8][64];
    __shared__ __align__(16) int   sidx [8][64];
    int gw   = (blockIdx.x * blockDim.x + threadIdx.x) >> 5;
    int lane = threadIdx.x & 31;
    int w    = (threadIdx.x >> 5);
    if (gw >= Nn) return;
    const int start = g_rowptr[gw];
    const int end   = g_rowptr[gw + 1];
    const int deg   = end - start;
    float m, inv_den;
    softmax_coefs(gw, start, end, g_as, g_ad[gw], scoef[w], sidx[w], lane, m, inv_den);
    const int nreg = deg < 64 ? deg : 64;
    const float* wc = scoef[w];
    const int*   wi = sidx[w];

    float2 a = make_float2(0.f, 0.f);
    int j = 0;
    for (; j + 8 <= nreg; j += 8) {
        float4 cA = *(const float4*)&wc[j];
        float4 cB = *(const float4*)&wc[j + 4];
        int4   iA = *(const int4*)&wi[j];
        int4   iB = *(const int4*)&wi[j + 4];
        float2 r0 = ((const float2*)(h + (size_t)iA.x * 64))[lane];
        float2 r1 = ((const float2*)(h + (size_t)iA.y * 64))[lane];
        float2 r2 = ((const float2*)(h + (size_t)iA.z * 64))[lane];
        float2 r3 = ((const float2*)(h + (size_t)iA.w * 64))[lane];
        float2 r4 = ((const float2*)(h + (size_t)iB.x * 64))[lane];
        float2 r5 = ((const float2*)(h + (size_t)iB.y * 64))[lane];
        float2 r6 = ((const float2*)(h + (size_t)iB.z * 64))[lane];
        float2 r7 = ((const float2*)(h + (size_t)iB.w * 64))[lane];
        a.x += cA.x * r0.x + cA.y * r1.x + cA.z * r2.x + cA.w * r3.x
             + cB.x * r4.x + cB.y * r5.x + cB.z * r6.x + cB.w * r7.x;
        a.y += cA.x * r0.y + cA.y * r1.y + cA.z * r2.y + cA.w * r3.y
             + cB.x * r4.y + cB.y * r5.y + cB.z * r6.y + cB.w * r7.y;
    }
    for (; j < nreg; j++) {
        float ca = wc[j];
        int   s0 = wi[j];
        float2 r0 = ((const float2*)(h + (size_t)s0 * 64))[lane];
        a.x += ca * r0.x; a.y += ca * r0.y;
    }
    for (int e2 = start + 64; e2 < end; e2++) {
        int sn = g_csr[e2];
        float c = __expf(lrelu(g_as[sn] + g_ad[gw]) - m) * inv_den;
        float2 r0 = ((const float2*)(h + (size_t)sn * 64))[lane];
        a.x += c * r0.x; a.y += c * r0.y;
    }
    float2 bvv = ((const float2*)bias)[lane];
    a.x = elu1(a.x + bvv.x); a.y = elu1(a.y + bvv.y);
    float2 wv = ((const float2*)W3)[lane];
    float dot = a.x * wv.x + a.y * wv.y;
    #pragma unroll
    for (int off = 16; off; off >>= 1) dot += __shfl_xor_sync(FULL, dot, off);
    if (lane == 0) {
        out[gw]   = dot;
        g_as3[gw] = dot * as3[0];
        g_ad3[gw] = dot * ad3[0];
    }
}

// ---------------- agg layer 3 (scalar) ------------------------------------------
__global__ void agg1_k(const float* __restrict__ h, float* __restrict__ out,
                       const float* __restrict__ bias) {
    int gw   = (blockIdx.x * blockDim.x + threadIdx.x) >> 5;
    int lane = threadIdx.x & 31;
    if (gw >= Nn) return;
    const int start = g_rowptr[gw];
    const int end   = g_rowptr[gw + 1];
    const float adn = g_ad3[gw];

    float m = -3.0e38f, s = 0.f;
    for (int e = start + lane; e < end; e += 32) {
        float l = lrelu(g_as3[g_csr[e]] + adn);
        float mn = fmaxf(m, l);
        s = s * __expf(m - mn) + __expf(l - mn);
        m = mn;
    }
    #pragma unroll
    for (int off = 16; off; off >>= 1) {
        float mo = __shfl_xor_sync(FULL, m, off);
        float so = __shfl_xor_sync(FULL, s, off);
        float mn = fmaxf(m, mo);
        s = s * __expf(m - mn) + so * __expf(mo - mn);
        m = mn;
    }
    const float inv_den = 1.f / s;
    float a = 0.f;
    for (int e = start + lane; e < end; e += 32) {
        int sn = g_csr[e];
        float c = __expf(lrelu(g_as3[sn] + adn) - m) * inv_den;
        a += c * h[sn];
    }
    #pragma unroll
    for (int off = 16; off; off >>= 1) a += __shfl_xor_sync(FULL, a, off);
    if (lane == 0) out[gw] = a + bias[0];
}

// =============================== launcher ======================================
extern "C" void kernel_launch(void* const* d_in, const int* in_sizes, int n_in,
                              void* d_out, int out_size) {
    const float* x  = (const float*)d_in[0];
    const int*   ei = (const int*)d_in[1];
    const float *W1 = (const float*)d_in[2],  *as1 = (const float*)d_in[3],
                *ad1 = (const float*)d_in[4], *b1  = (const float*)d_in[5];
    const float *W2 = (const float*)d_in[6],  *as2 = (const float*)d_in[7],
                *ad2 = (const float*)d_in[8], *b2  = (const float*)d_in[9];
    const float *W3 = (const float*)d_in[10], *as3 = (const float*)d_in[11],
                *ad3 = (const float*)d_in[12], *b3 = (const float*)d_in[13];
    float* out = (float*)d_out;

    unsigned short *pxh, *pxl, *phh, *phl, *pw1h, *pw1l, *pw2h, *pw2l;
    float *po, *py;
    cudaGetSymbolAddress((void**)&pxh, g_xh);
    cudaGetSymbolAddress((void**)&pxl, g_xl);
    cudaGetSymbolAddress((void**)&phh, g_hh);
    cudaGetSymbolAddress((void**)&phl, g_hl);
    cudaGetSymbolAddress((void**)&pw1h, g_w1h);
    cudaGetSymbolAddress((void**)&pw1l, g_w1l);
    cudaGetSymbolAddress((void**)&pw2h, g_w2h);
    cudaGetSymbolAddress((void**)&pw2l, g_w2l);
    cudaGetSymbolAddress((void**)&po, g_o);
    cudaGetSymbolAddress((void**)&py, g_y);

    const int TB = 256;
    const int warpNodeBlk = (Nn * 32 + TB - 1) / TB;
    const int edge4Blk    = (Ereal / 4 + TB - 1) / TB;
    const int alphaBlk    = (Nn + 31) / 32;
    const int place1024   = (Ereal / 4 + 1023) / 1024;
    const int mRows = (Nn + 127) / 128;

    prep_count<<<edge4Blk + W1BLK + W2BLK + PBLK, TB>>>(ei, W1, as1, ad1, W2, edge4Blk);
    scan_alpha_place<<<NBLK + alphaBlk + place1024, 1024>>>(x, ei, alphaBlk);

    // ---- layer 1 (aggregate-then-transform): 128 -> 256 ----
    agg128_k<<<warpNodeBlk, TB>>>(x);
    {
        dim3 grid(D1 / 64, mRows);
        gemm1_k<<<grid, 256>>>(pxh, pxl, pw1h, pw1l, phh, phl, b1, Nn);
    }
    // ---- layer 2: 256 -> 64 ----
    {
        dim3 grid(1, mRows);
        gemm2_k<<<grid, 256>>>(phh, phl, pw2h, pw2l, po, as2, ad2, Nn);
        agg64_k<<<warpNodeBlk, TB>>>(po, py, b2, W3, as3, ad3);
    }
    // ---- layer 3: 64 -> 1 ----
    agg1_k<<<warpNodeBlk, TB>>>(py, out, b3);
}